// round 1
// baseline (speedup 1.0000x reference)
#include <cuda_runtime.h>
#include <math.h>

// Problem constants
static constexpr int Bc = 2, Sc = 2048, Hc = 2048, NHc = 16, HDc = 128, BSZ = 256;
static constexpr int Mc = Bc * Sc;  // 4096
static constexpr float SCALE = 0.08838834764831845f;  // 1/sqrt(128)

// Scratch (device globals — no allocation allowed)
__device__ float g_q[Bc * Sc * Hc];
__device__ float g_k[Bc * Sc * Hc];
__device__ float g_v[Bc * Sc * Hc];
__device__ float g_ao[Bc * Sc * Hc];

// ---------------------------------------------------------------------------
// GEMM: C[m][n] = sum_k A[m][k] * W[n][k]   (A row-major [M,K], W row-major [N,K])
// 128x128 tile, BK=16, 256 threads, 8x8 micro-tile.
// ---------------------------------------------------------------------------
__global__ __launch_bounds__(256) void gemm_abt(const float* __restrict__ A,
                                                const float* __restrict__ W,
                                                float* __restrict__ C,
                                                int Md, int Nd, int Kd) {
    __shared__ float As[16 * 132];
    __shared__ float Bs[16 * 132];
    const int m0 = blockIdx.y * 128;
    const int n0 = blockIdx.x * 128;
    const int tid = threadIdx.x;
    const int tr = tid >> 4;   // 0..15
    const int tc = tid & 15;   // 0..15

    float acc[8][8];
#pragma unroll
    for (int i = 0; i < 8; ++i)
#pragma unroll
        for (int j = 0; j < 8; ++j) acc[i][j] = 0.f;

    for (int k0 = 0; k0 < Kd; k0 += 16) {
#pragma unroll
        for (int i = 0; i < 2; ++i) {
            int t = tid + i * 256;
            int row = t >> 2;
            int c = (t & 3) * 4;
            float4 a = *(const float4*)(A + (size_t)(m0 + row) * Kd + k0 + c);
            As[(c + 0) * 132 + row] = a.x;
            As[(c + 1) * 132 + row] = a.y;
            As[(c + 2) * 132 + row] = a.z;
            As[(c + 3) * 132 + row] = a.w;
            float4 b = *(const float4*)(W + (size_t)(n0 + row) * Kd + k0 + c);
            Bs[(c + 0) * 132 + row] = b.x;
            Bs[(c + 1) * 132 + row] = b.y;
            Bs[(c + 2) * 132 + row] = b.z;
            Bs[(c + 3) * 132 + row] = b.w;
        }
        __syncthreads();
#pragma unroll
        for (int k = 0; k < 16; ++k) {
            float a[8], b[8];
            *(float4*)(a + 0) = *(float4*)&As[k * 132 + tr * 8 + 0];
            *(float4*)(a + 4) = *(float4*)&As[k * 132 + tr * 8 + 4];
            *(float4*)(b + 0) = *(float4*)&Bs[k * 132 + tc * 8 + 0];
            *(float4*)(b + 4) = *(float4*)&Bs[k * 132 + tc * 8 + 4];
#pragma unroll
            for (int i = 0; i < 8; ++i)
#pragma unroll
                for (int j = 0; j < 8; ++j) acc[i][j] += a[i] * b[j];
        }
        __syncthreads();
    }
#pragma unroll
    for (int i = 0; i < 8; ++i) {
        float4 o0 = make_float4(acc[i][0], acc[i][1], acc[i][2], acc[i][3]);
        float4 o1 = make_float4(acc[i][4], acc[i][5], acc[i][6], acc[i][7]);
        float* cp = C + (size_t)(m0 + tr * 8 + i) * Nd + n0 + tc * 8;
        *(float4*)(cp + 0) = o0;
        *(float4*)(cp + 4) = o1;
    }
}

// ---------------------------------------------------------------------------
// Block-softmax attention.
// Grid: (S/64, NH, B). 256 threads. Per CTA: 64 queries of one head.
// For each kv block j <= bi (bi = query block idx in units of 256):
//   S = Q K^T * scale   (diag-block causal mask)
//   per-row softmax over this block's 256 keys
//   O += W V
// Final: O /= (bi+1 + 1e-6)   [each block softmax sums to exactly 1]
// SMEM: Qts[128][65] (d-major), Kts[128][65] / Vs[64][132] (union), Ss[64][260]
// ---------------------------------------------------------------------------
__global__ __launch_bounds__(256) void attn_kernel(const float* __restrict__ Q,
                                                   const float* __restrict__ K,
                                                   const float* __restrict__ V,
                                                   float* __restrict__ O) {
    extern __shared__ float sm[];
    float* Qts = sm;                      // 128*65 = 8320
    float* Kts = sm + 8320;               // max(128*65, 64*132) = 8448
    float* Ss = sm + 8320 + 8448;         // 64*260 = 16640

    const int qt = blockIdx.x;
    const int h = blockIdx.y;
    const int b = blockIdx.z;
    const int q0g = qt * 64;
    const int bi = q0g >> 8;   // /256
    const int nb = bi + 1;
    const int tid = threadIdx.x;
    const size_t base = (size_t)b * Sc * Hc + (size_t)h * HDc;

    // Load Q tile transposed: Qts[d][r]
#pragma unroll
    for (int i = 0; i < 8; ++i) {
        int t = tid + i * 256;
        int r = t >> 5;
        int d = (t & 31) * 4;
        float4 a = *(const float4*)(Q + base + (size_t)(q0g + r) * Hc + d);
        Qts[(d + 0) * 65 + r] = a.x;
        Qts[(d + 1) * 65 + r] = a.y;
        Qts[(d + 2) * 65 + r] = a.z;
        Qts[(d + 3) * 65 + r] = a.w;
    }

    const int tqg = tid >> 4, tkg = tid & 15;
    const int sq0 = tqg * 4, sk0 = tkg * 4;
    const int oq0 = tqg * 4, od0 = tkg * 8;
    const int wid = tid >> 5, lane = tid & 31;

    float oacc[4][8];
#pragma unroll
    for (int i = 0; i < 4; ++i)
#pragma unroll
        for (int j = 0; j < 8; ++j) oacc[i][j] = 0.f;

    for (int j = 0; j <= bi; ++j) {
        const int kabs0 = j * BSZ;

        // ---- GEMM1: scores for this 256-key block, in 4 chunks of 64 keys ----
        for (int c = 0; c < 4; ++c) {
            __syncthreads();
#pragma unroll
            for (int i = 0; i < 8; ++i) {
                int t = tid + i * 256;
                int r = t >> 5;
                int d = (t & 31) * 4;
                float4 a = *(const float4*)(K + base + (size_t)(kabs0 + c * 64 + r) * Hc + d);
                Kts[(d + 0) * 65 + r] = a.x;
                Kts[(d + 1) * 65 + r] = a.y;
                Kts[(d + 2) * 65 + r] = a.z;
                Kts[(d + 3) * 65 + r] = a.w;
            }
            __syncthreads();
            float acc[4][4];
#pragma unroll
            for (int i = 0; i < 4; ++i)
#pragma unroll
                for (int jj = 0; jj < 4; ++jj) acc[i][jj] = 0.f;
            for (int d = 0; d < 128; ++d) {
                float aq[4], bk[4];
#pragma unroll
                for (int i = 0; i < 4; ++i) aq[i] = Qts[d * 65 + sq0 + i];
#pragma unroll
                for (int i = 0; i < 4; ++i) bk[i] = Kts[d * 65 + sk0 + i];
#pragma unroll
                for (int i = 0; i < 4; ++i)
#pragma unroll
                    for (int jj = 0; jj < 4; ++jj) acc[i][jj] += aq[i] * bk[jj];
            }
#pragma unroll
            for (int i = 0; i < 4; ++i) {
                float4 w4 = make_float4(acc[i][0] * SCALE, acc[i][1] * SCALE,
                                        acc[i][2] * SCALE, acc[i][3] * SCALE);
                *(float4*)&Ss[(sq0 + i) * 260 + c * 64 + sk0] = w4;
            }
        }
        __syncthreads();

        // ---- Per-block softmax (8 rows per warp) ----
        const bool diag = (j == bi);
#pragma unroll
        for (int rr = 0; rr < 8; ++rr) {
            int r = wid * 8 + rr;
            int qi = q0g + r;
            float vals[8];
            float mx = -1e30f;
#pragma unroll
            for (int c = 0; c < 8; ++c) {
                int kk = c * 32 + lane;
                float s0 = Ss[r * 260 + kk];
                if (diag && (kabs0 + kk) > qi) s0 = -1e30f;
                vals[c] = s0;
                mx = fmaxf(mx, s0);
            }
#pragma unroll
            for (int off = 16; off >= 1; off >>= 1)
                mx = fmaxf(mx, __shfl_xor_sync(0xffffffffu, mx, off));
            float l = 0.f;
#pragma unroll
            for (int c = 0; c < 8; ++c) {
                float p = (vals[c] <= -1e29f) ? 0.f : __expf(vals[c] - mx);
                vals[c] = p;
                l += p;
            }
#pragma unroll
            for (int off = 16; off >= 1; off >>= 1)
                l += __shfl_xor_sync(0xffffffffu, l, off);
            float inv = 1.f / l;
#pragma unroll
            for (int c = 0; c < 8; ++c) Ss[r * 260 + c * 32 + lane] = vals[c] * inv;
        }
        __syncthreads();

        // ---- GEMM2: O += W V, 4 chunks of 64 keys ----
        float* Vs = Kts;  // reuse
        for (int c = 0; c < 4; ++c) {
#pragma unroll
            for (int i = 0; i < 8; ++i) {
                int t = tid + i * 256;
                int r = t >> 5;
                int d = (t & 31) * 4;
                *(float4*)&Vs[r * 132 + d] =
                    *(const float4*)(V + base + (size_t)(kabs0 + c * 64 + r) * Hc + d);
            }
            __syncthreads();
            for (int kk = 0; kk < 64; ++kk) {
                float w[4];
#pragma unroll
                for (int i = 0; i < 4; ++i) w[i] = Ss[(oq0 + i) * 260 + c * 64 + kk];
                float4 v0 = *(float4*)&Vs[kk * 132 + od0 + 0];
                float4 v1 = *(float4*)&Vs[kk * 132 + od0 + 4];
                float vv[8] = {v0.x, v0.y, v0.z, v0.w, v1.x, v1.y, v1.z, v1.w};
#pragma unroll
                for (int i = 0; i < 4; ++i)
#pragma unroll
                    for (int jj = 0; jj < 8; ++jj) oacc[i][jj] += w[i] * vv[jj];
            }
            __syncthreads();
        }
    }

    // ---- Normalize and write out (merged [b,s,h,d] layout) ----
    const float invn = 1.f / ((float)nb + 1e-6f);
#pragma unroll
    for (int i = 0; i < 4; ++i) {
        float4 o0 = make_float4(oacc[i][0] * invn, oacc[i][1] * invn,
                                oacc[i][2] * invn, oacc[i][3] * invn);
        float4 o1 = make_float4(oacc[i][4] * invn, oacc[i][5] * invn,
                                oacc[i][6] * invn, oacc[i][7] * invn);
        float* op = O + base + (size_t)(q0g + oq0 + i) * Hc + od0;
        *(float4*)(op + 0) = o0;
        *(float4*)(op + 4) = o1;
    }
}

// ---------------------------------------------------------------------------
extern "C" void kernel_launch(void* const* d_in, const int* in_sizes, int n_in,
                              void* d_out, int out_size) {
    const float* hs = (const float*)d_in[0];
    const float* Wq = (const float*)d_in[1];
    const float* Wk = (const float*)d_in[2];
    const float* Wv = (const float*)d_in[3];
    const float* Wo = (const float*)d_in[4];
    float* out = (float*)d_out;

    float *qp, *kp, *vp, *aop;
    cudaGetSymbolAddress((void**)&qp, g_q);
    cudaGetSymbolAddress((void**)&kp, g_k);
    cudaGetSymbolAddress((void**)&vp, g_v);
    cudaGetSymbolAddress((void**)&aop, g_ao);

    static int smem_set = 0;
    const int attn_smem = (8320 + 8448 + 16640) * 4;  // 133632 B
    if (!smem_set) {
        cudaFuncSetAttribute(attn_kernel, cudaFuncAttributeMaxDynamicSharedMemorySize,
                             attn_smem);
        smem_set = 1;
    }

    dim3 gg(Hc / 128, Mc / 128);  // (16, 32)
    gemm_abt<<<gg, 256>>>(hs, Wq, qp, Mc, Hc, Hc);
    gemm_abt<<<gg, 256>>>(hs, Wk, kp, Mc, Hc, Hc);
    gemm_abt<<<gg, 256>>>(hs, Wv, vp, Mc, Hc, Hc);

    dim3 ga(Sc / 64, NHc, Bc);  // (32, 16, 2)
    attn_kernel<<<ga, 256, attn_smem>>>(qp, kp, vp, aop);

    gemm_abt<<<gg, 256>>>(aop, Wo, out, Mc, Hc, Hc);
}

// round 3
// speedup vs baseline: 1.7867x; 1.7867x over previous
#include <cuda_runtime.h>
#include <cstdint>
#include <math.h>

// Problem constants
static constexpr int Bc = 2, Sc = 2048, Hc = 2048, NHc = 16, HDc = 128, BSZ = 256;
static constexpr int Mc = Bc * Sc;  // 4096
static constexpr float SCALE = 0.08838834764831845f;  // 1/sqrt(128)

// Scratch (device globals — no allocation allowed)
__device__ float g_q[Bc * Sc * Hc];
__device__ float g_k[Bc * Sc * Hc];
__device__ float g_v[Bc * Sc * Hc];
__device__ float g_ao[Bc * Sc * Hc];

// ---------------------------------------------------------------------------
// helpers
// ---------------------------------------------------------------------------
__device__ __forceinline__ uint32_t smem_u32(const void* p) {
    uint32_t a;
    asm("{ .reg .u64 t; cvta.to.shared.u64 t, %1; cvt.u32.u64 %0, t; }"
        : "=r"(a) : "l"(p));
    return a;
}
__device__ __forceinline__ uint32_t f2tf32(float x) {
    uint32_t r;
    asm("cvt.rna.tf32.f32 %0, %1;" : "=r"(r) : "f"(x));
    return r;
}
__device__ __forceinline__ void ldsm_x4(uint32_t* r, uint32_t addr) {
    asm volatile("ldmatrix.sync.aligned.m8n8.x4.shared.b16 {%0,%1,%2,%3}, [%4];"
                 : "=r"(r[0]), "=r"(r[1]), "=r"(r[2]), "=r"(r[3]) : "r"(addr));
}
__device__ __forceinline__ void mma_tf32(float* d, const uint32_t* a,
                                         uint32_t b0, uint32_t b1) {
    asm volatile(
        "mma.sync.aligned.m16n8k8.row.col.f32.tf32.tf32.f32 "
        "{%0,%1,%2,%3}, {%4,%5,%6,%7}, {%8,%9}, {%0,%1,%2,%3};"
        : "+f"(d[0]), "+f"(d[1]), "+f"(d[2]), "+f"(d[3])
        : "r"(a[0]), "r"(a[1]), "r"(a[2]), "r"(a[3]), "r"(b0), "r"(b1));
}

// ---------------------------------------------------------------------------
// tf32 mma.sync GEMM: C[m][n] = sum_k A[m][k] * W[n][k]
// CTA tile 128x128, BK=32, 256 threads (8 warps, 2x4), warp tile 64x32.
// smem per buffer: A 128 rows x 36 floats (pad), B same. 2 buffers.
// Inputs rounded to tf32 (cvt.rna) in the load path -> unbiased error ~3e-4.
// ---------------------------------------------------------------------------
static constexpr int ROWSTRIDE = 36;                      // floats
static constexpr int TILE_BYTES = 128 * ROWSTRIDE * 4;    // 18432
static constexpr int BUF_BYTES = 2 * TILE_BYTES;          // A+B
static constexpr int GEMM_SMEM = 2 * BUF_BYTES;           // 73728

__global__ __launch_bounds__(256, 2) void gemm_mma(const float* __restrict__ A,
                                                   const float* __restrict__ W,
                                                   float* __restrict__ C,
                                                   int Kd, int Nd) {
    extern __shared__ __align__(128) char smem[];
    const uint32_t sb = smem_u32(smem);
    const int tid = threadIdx.x;
    const int lane = tid & 31, wid = tid >> 5;
    const int wm = wid >> 2, wn = wid & 3;
    const int m0 = blockIdx.y * 128, n0 = blockIdx.x * 128;
    const int NKB = Kd / 32;  // 64

    // Global load slots: 4 float4 of A + 4 of B per thread per K-block.
    const int grow = tid >> 3;        // 0..31 base; +32 per i? no: id = tid + i*256
    const int gch = tid & 7;
    const float* pA[4];
    const float* pB[4];
    uint32_t stoff[4];
#pragma unroll
    for (int i = 0; i < 4; ++i) {
        int id = tid + i * 256;
        int row = id >> 3, ch = id & 7;
        pA[i] = A + (size_t)(m0 + row) * Kd + ch * 4;
        pB[i] = W + (size_t)(n0 + row) * Kd + ch * 4;
        stoff[i] = row * (ROWSTRIDE * 4) + ch * 16;
    }
    (void)grow; (void)gch;

    // ldmatrix fragment addresses (byte offsets within a tile region)
    const int arow = wm * 64 + (lane & 7) + ((lane >> 3) & 1) * 8;
    const int acol = ((lane >> 4) & 1) * 4;
    const uint32_t aFragOff = arow * (ROWSTRIDE * 4) + acol * 4;
    const int brow = wn * 32 + (lane & 7) + ((lane >> 4) & 1) * 8;
    const int bcol = ((lane >> 3) & 1) * 4;
    const uint32_t bFragOff = brow * (ROWSTRIDE * 4) + bcol * 4;

    float acc[4][4][4];
#pragma unroll
    for (int t = 0; t < 4; ++t)
#pragma unroll
        for (int u = 0; u < 4; ++u)
#pragma unroll
            for (int e = 0; e < 4; ++e) acc[t][u][e] = 0.f;

    // Prologue: load K-block 0 into registers
    float4 ra[4], rb[4];
#pragma unroll
    for (int i = 0; i < 4; ++i) { ra[i] = *(const float4*)pA[i]; rb[i] = *(const float4*)pB[i]; }

    for (int kb = 0; kb < NKB; ++kb) {
        const uint32_t bufo = (kb & 1) ? BUF_BYTES : 0;
        const uint32_t sA = sb + bufo;
        const uint32_t sB = sb + bufo + TILE_BYTES;
        // store (with tf32 rounding)
#pragma unroll
        for (int i = 0; i < 4; ++i) {
            asm volatile("st.shared.v4.b32 [%0], {%1,%2,%3,%4};"
                         :: "r"(sA + stoff[i]), "r"(f2tf32(ra[i].x)), "r"(f2tf32(ra[i].y)),
                            "r"(f2tf32(ra[i].z)), "r"(f2tf32(ra[i].w)) : "memory");
            asm volatile("st.shared.v4.b32 [%0], {%1,%2,%3,%4};"
                         :: "r"(sB + stoff[i]), "r"(f2tf32(rb[i].x)), "r"(f2tf32(rb[i].y)),
                            "r"(f2tf32(rb[i].z)), "r"(f2tf32(rb[i].w)) : "memory");
        }
        __syncthreads();
        // prefetch next K-block
        if (kb + 1 < NKB) {
#pragma unroll
            for (int i = 0; i < 4; ++i) {
                ra[i] = *(const float4*)(pA[i] + (kb + 1) * 32);
                rb[i] = *(const float4*)(pB[i] + (kb + 1) * 32);
            }
        }
        // compute 4 k8-steps
#pragma unroll
        for (int ks = 0; ks < 4; ++ks) {
            uint32_t af[4][4];
#pragma unroll
            for (int t = 0; t < 4; ++t)
                ldsm_x4(af[t], sA + aFragOff + t * (16 * ROWSTRIDE * 4) + ks * 32);
            uint32_t bf[2][4];
#pragma unroll
            for (int p = 0; p < 2; ++p)
                ldsm_x4(bf[p], sB + bFragOff + p * (16 * ROWSTRIDE * 4) + ks * 32);
#pragma unroll
            for (int t = 0; t < 4; ++t) {
                mma_tf32(acc[t][0], af[t], bf[0][0], bf[0][1]);
                mma_tf32(acc[t][1], af[t], bf[0][2], bf[0][3]);
                mma_tf32(acc[t][2], af[t], bf[1][0], bf[1][1]);
                mma_tf32(acc[t][3], af[t], bf[1][2], bf[1][3]);
            }
        }
        __syncthreads();
    }

    // Epilogue: write C
    const int crow = lane >> 2, ccol = (lane & 3) * 2;
#pragma unroll
    for (int t = 0; t < 4; ++t) {
        int r0 = m0 + wm * 64 + t * 16 + crow;
#pragma unroll
        for (int u = 0; u < 4; ++u) {
            int c = n0 + wn * 32 + u * 8 + ccol;
            float2 lo = make_float2(acc[t][u][0], acc[t][u][1]);
            float2 hi = make_float2(acc[t][u][2], acc[t][u][3]);
            *(float2*)(C + (size_t)r0 * Nd + c) = lo;
            *(float2*)(C + (size_t)(r0 + 8) * Nd + c) = hi;
        }
    }
}

// ---------------------------------------------------------------------------
// Block-softmax attention (unchanged from R1).
// ---------------------------------------------------------------------------
__global__ __launch_bounds__(256) void attn_kernel(const float* __restrict__ Q,
                                                   const float* __restrict__ K,
                                                   const float* __restrict__ V,
                                                   float* __restrict__ O) {
    extern __shared__ float sm[];
    float* Qts = sm;                      // 128*65 = 8320
    float* Kts = sm + 8320;               // max(128*65, 64*132) = 8448
    float* Ss = sm + 8320 + 8448;         // 64*260 = 16640

    const int qt = blockIdx.x;
    const int h = blockIdx.y;
    const int b = blockIdx.z;
    const int q0g = qt * 64;
    const int bi = q0g >> 8;
    const int nb = bi + 1;
    const int tid = threadIdx.x;
    const size_t base = (size_t)b * Sc * Hc + (size_t)h * HDc;

#pragma unroll
    for (int i = 0; i < 8; ++i) {
        int t = tid + i * 256;
        int r = t >> 5;
        int d = (t & 31) * 4;
        float4 a = *(const float4*)(Q + base + (size_t)(q0g + r) * Hc + d);
        Qts[(d + 0) * 65 + r] = a.x;
        Qts[(d + 1) * 65 + r] = a.y;
        Qts[(d + 2) * 65 + r] = a.z;
        Qts[(d + 3) * 65 + r] = a.w;
    }

    const int tqg = tid >> 4, tkg = tid & 15;
    const int sq0 = tqg * 4, sk0 = tkg * 4;
    const int oq0 = tqg * 4, od0 = tkg * 8;
    const int wid = tid >> 5, lane = tid & 31;

    float oacc[4][8];
#pragma unroll
    for (int i = 0; i < 4; ++i)
#pragma unroll
        for (int j = 0; j < 8; ++j) oacc[i][j] = 0.f;

    for (int j = 0; j <= bi; ++j) {
        const int kabs0 = j * BSZ;

        for (int c = 0; c < 4; ++c) {
            __syncthreads();
#pragma unroll
            for (int i = 0; i < 8; ++i) {
                int t = tid + i * 256;
                int r = t >> 5;
                int d = (t & 31) * 4;
                float4 a = *(const float4*)(K + base + (size_t)(kabs0 + c * 64 + r) * Hc + d);
                Kts[(d + 0) * 65 + r] = a.x;
                Kts[(d + 1) * 65 + r] = a.y;
                Kts[(d + 2) * 65 + r] = a.z;
                Kts[(d + 3) * 65 + r] = a.w;
            }
            __syncthreads();
            float acc[4][4];
#pragma unroll
            for (int i = 0; i < 4; ++i)
#pragma unroll
                for (int jj = 0; jj < 4; ++jj) acc[i][jj] = 0.f;
            for (int d = 0; d < 128; ++d) {
                float aq[4], bk[4];
#pragma unroll
                for (int i = 0; i < 4; ++i) aq[i] = Qts[d * 65 + sq0 + i];
#pragma unroll
                for (int i = 0; i < 4; ++i) bk[i] = Kts[d * 65 + sk0 + i];
#pragma unroll
                for (int i = 0; i < 4; ++i)
#pragma unroll
                    for (int jj = 0; jj < 4; ++jj) acc[i][jj] += aq[i] * bk[jj];
            }
#pragma unroll
            for (int i = 0; i < 4; ++i) {
                float4 w4 = make_float4(acc[i][0] * SCALE, acc[i][1] * SCALE,
                                        acc[i][2] * SCALE, acc[i][3] * SCALE);
                *(float4*)&Ss[(sq0 + i) * 260 + c * 64 + sk0] = w4;
            }
        }
        __syncthreads();

        const bool diag = (j == bi);
#pragma unroll
        for (int rr = 0; rr < 8; ++rr) {
            int r = wid * 8 + rr;
            int qi = q0g + r;
            float vals[8];
            float mx = -1e30f;
#pragma unroll
            for (int c = 0; c < 8; ++c) {
                int kk = c * 32 + lane;
                float s0 = Ss[r * 260 + kk];
                if (diag && (kabs0 + kk) > qi) s0 = -1e30f;
                vals[c] = s0;
                mx = fmaxf(mx, s0);
            }
#pragma unroll
            for (int off = 16; off >= 1; off >>= 1)
                mx = fmaxf(mx, __shfl_xor_sync(0xffffffffu, mx, off));
            float l = 0.f;
#pragma unroll
            for (int c = 0; c < 8; ++c) {
                float p = (vals[c] <= -1e29f) ? 0.f : __expf(vals[c] - mx);
                vals[c] = p;
                l += p;
            }
#pragma unroll
            for (int off = 16; off >= 1; off >>= 1)
                l += __shfl_xor_sync(0xffffffffu, l, off);
            float inv = 1.f / l;
#pragma unroll
            for (int c = 0; c < 8; ++c) Ss[r * 260 + c * 32 + lane] = vals[c] * inv;
        }
        __syncthreads();

        float* Vs = Kts;
        for (int c = 0; c < 4; ++c) {
#pragma unroll
            for (int i = 0; i < 8; ++i) {
                int t = tid + i * 256;
                int r = t >> 5;
                int d = (t & 31) * 4;
                *(float4*)&Vs[r * 132 + d] =
                    *(const float4*)(V + base + (size_t)(kabs0 + c * 64 + r) * Hc + d);
            }
            __syncthreads();
            for (int kk = 0; kk < 64; ++kk) {
                float w[4];
#pragma unroll
                for (int i = 0; i < 4; ++i) w[i] = Ss[(oq0 + i) * 260 + c * 64 + kk];
                float4 v0 = *(float4*)&Vs[kk * 132 + od0 + 0];
                float4 v1 = *(float4*)&Vs[kk * 132 + od0 + 4];
                float vv[8] = {v0.x, v0.y, v0.z, v0.w, v1.x, v1.y, v1.z, v1.w};
#pragma unroll
                for (int i = 0; i < 4; ++i)
#pragma unroll
                    for (int jj = 0; jj < 8; ++jj) oacc[i][jj] += w[i] * vv[jj];
            }
            __syncthreads();
        }
    }

    const float invn = 1.f / ((float)nb + 1e-6f);
#pragma unroll
    for (int i = 0; i < 4; ++i) {
        float4 o0 = make_float4(oacc[i][0] * invn, oacc[i][1] * invn,
                                oacc[i][2] * invn, oacc[i][3] * invn);
        float4 o1 = make_float4(oacc[i][4] * invn, oacc[i][5] * invn,
                                oacc[i][6] * invn, oacc[i][7] * invn);
        float* op = O + base + (size_t)(q0g + oq0 + i) * Hc + od0;
        *(float4*)(op + 0) = o0;
        *(float4*)(op + 4) = o1;
    }
}

// ---------------------------------------------------------------------------
extern "C" void kernel_launch(void* const* d_in, const int* in_sizes, int n_in,
                              void* d_out, int out_size) {
    const float* hs = (const float*)d_in[0];
    const float* Wq = (const float*)d_in[1];
    const float* Wk = (const float*)d_in[2];
    const float* Wv = (const float*)d_in[3];
    const float* Wo = (const float*)d_in[4];
    float* out = (float*)d_out;

    float *qp, *kp, *vp, *aop;
    cudaGetSymbolAddress((void**)&qp, g_q);
    cudaGetSymbolAddress((void**)&kp, g_k);
    cudaGetSymbolAddress((void**)&vp, g_v);
    cudaGetSymbolAddress((void**)&aop, g_ao);

    static int smem_set = 0;
    const int attn_smem = (8320 + 8448 + 16640) * 4;  // 133632 B
    if (!smem_set) {
        cudaFuncSetAttribute(attn_kernel, cudaFuncAttributeMaxDynamicSharedMemorySize,
                             attn_smem);
        cudaFuncSetAttribute(gemm_mma, cudaFuncAttributeMaxDynamicSharedMemorySize,
                             GEMM_SMEM);
        smem_set = 1;
    }

    dim3 gg(Hc / 128, Mc / 128);  // (16, 32)
    gemm_mma<<<gg, 256, GEMM_SMEM>>>(hs, Wq, qp, Hc, Hc);
    gemm_mma<<<gg, 256, GEMM_SMEM>>>(hs, Wk, kp, Hc, Hc);
    gemm_mma<<<gg, 256, GEMM_SMEM>>>(hs, Wv, vp, Hc, Hc);

    dim3 ga(Sc / 64, NHc, Bc);  // (32, 16, 2)
    attn_kernel<<<ga, 256, attn_smem>>>(qp, kp, vp, aop);

    gemm_mma<<<gg, 256, GEMM_SMEM>>>(aop, Wo, out, Hc, Hc);
}

// round 4
// speedup vs baseline: 2.8820x; 1.6130x over previous
#include <cuda_runtime.h>
#include <cstdint>
#include <math.h>

// Problem constants
static constexpr int Bc = 2, Sc = 2048, Hc = 2048, NHc = 16, HDc = 128, BSZ = 256;
static constexpr int Mc = Bc * Sc;  // 4096
static constexpr float SCALE = 0.08838834764831845f;  // 1/sqrt(128)

// Scratch (device globals — no allocation allowed)
__device__ float g_q[Bc * Sc * Hc];
__device__ float g_k[Bc * Sc * Hc];
__device__ float g_v[Bc * Sc * Hc];
__device__ float g_ao[Bc * Sc * Hc];

// ---------------------------------------------------------------------------
// helpers
// ---------------------------------------------------------------------------
__device__ __forceinline__ uint32_t smem_u32(const void* p) {
    uint32_t a;
    asm("{ .reg .u64 t; cvta.to.shared.u64 t, %1; cvt.u32.u64 %0, t; }"
        : "=r"(a) : "l"(p));
    return a;
}
__device__ __forceinline__ uint32_t f2tf32(float x) {
    uint32_t r;
    asm("cvt.rna.tf32.f32 %0, %1;" : "=r"(r) : "f"(x));
    return r;
}
__device__ __forceinline__ void ldsm_x4(uint32_t* r, uint32_t addr) {
    asm volatile("ldmatrix.sync.aligned.m8n8.x4.shared.b16 {%0,%1,%2,%3}, [%4];"
                 : "=r"(r[0]), "=r"(r[1]), "=r"(r[2]), "=r"(r[3]) : "r"(addr));
}
__device__ __forceinline__ void mma_tf32(float* d, const uint32_t* a,
                                         uint32_t b0, uint32_t b1) {
    asm volatile(
        "mma.sync.aligned.m16n8k8.row.col.f32.tf32.tf32.f32 "
        "{%0,%1,%2,%3}, {%4,%5,%6,%7}, {%8,%9}, {%0,%1,%2,%3};"
        : "+f"(d[0]), "+f"(d[1]), "+f"(d[2]), "+f"(d[3])
        : "r"(a[0]), "r"(a[1]), "r"(a[2]), "r"(a[3]), "r"(b0), "r"(b1));
}
__device__ __forceinline__ void sts4_tf32(uint32_t addr, float4 v) {
    asm volatile("st.shared.v4.b32 [%0], {%1,%2,%3,%4};"
                 :: "r"(addr), "r"(f2tf32(v.x)), "r"(f2tf32(v.y)),
                    "r"(f2tf32(v.z)), "r"(f2tf32(v.w)) : "memory");
}

// ---------------------------------------------------------------------------
// tf32 mma.sync GEMM (unchanged, validated in R3)
// ---------------------------------------------------------------------------
static constexpr int ROWSTRIDE = 36;
static constexpr int TILE_BYTES = 128 * ROWSTRIDE * 4;
static constexpr int BUF_BYTES = 2 * TILE_BYTES;
static constexpr int GEMM_SMEM = 2 * BUF_BYTES;  // 73728

__global__ __launch_bounds__(256, 2) void gemm_mma(const float* __restrict__ A,
                                                   const float* __restrict__ W,
                                                   float* __restrict__ C,
                                                   int Kd, int Nd) {
    extern __shared__ __align__(128) char smem[];
    const uint32_t sb = smem_u32(smem);
    const int tid = threadIdx.x;
    const int lane = tid & 31, wid = tid >> 5;
    const int wm = wid >> 2, wn = wid & 3;
    const int m0 = blockIdx.y * 128, n0 = blockIdx.x * 128;
    const int NKB = Kd / 32;

    const float* pA[4];
    const float* pB[4];
    uint32_t stoff[4];
#pragma unroll
    for (int i = 0; i < 4; ++i) {
        int id = tid + i * 256;
        int row = id >> 3, ch = id & 7;
        pA[i] = A + (size_t)(m0 + row) * Kd + ch * 4;
        pB[i] = W + (size_t)(n0 + row) * Kd + ch * 4;
        stoff[i] = row * (ROWSTRIDE * 4) + ch * 16;
    }

    const int arow = wm * 64 + (lane & 7) + ((lane >> 3) & 1) * 8;
    const int acol = ((lane >> 4) & 1) * 4;
    const uint32_t aFragOff = arow * (ROWSTRIDE * 4) + acol * 4;
    const int brow = wn * 32 + (lane & 7) + ((lane >> 4) & 1) * 8;
    const int bcol = ((lane >> 3) & 1) * 4;
    const uint32_t bFragOff = brow * (ROWSTRIDE * 4) + bcol * 4;

    float acc[4][4][4];
#pragma unroll
    for (int t = 0; t < 4; ++t)
#pragma unroll
        for (int u = 0; u < 4; ++u)
#pragma unroll
            for (int e = 0; e < 4; ++e) acc[t][u][e] = 0.f;

    float4 ra[4], rb[4];
#pragma unroll
    for (int i = 0; i < 4; ++i) { ra[i] = *(const float4*)pA[i]; rb[i] = *(const float4*)pB[i]; }

    for (int kb = 0; kb < NKB; ++kb) {
        const uint32_t bufo = (kb & 1) ? BUF_BYTES : 0;
        const uint32_t sA = sb + bufo;
        const uint32_t sB = sb + bufo + TILE_BYTES;
#pragma unroll
        for (int i = 0; i < 4; ++i) {
            sts4_tf32(sA + stoff[i], ra[i]);
            sts4_tf32(sB + stoff[i], rb[i]);
        }
        __syncthreads();
        if (kb + 1 < NKB) {
#pragma unroll
            for (int i = 0; i < 4; ++i) {
                ra[i] = *(const float4*)(pA[i] + (kb + 1) * 32);
                rb[i] = *(const float4*)(pB[i] + (kb + 1) * 32);
            }
        }
#pragma unroll
        for (int ks = 0; ks < 4; ++ks) {
            uint32_t af[4][4];
#pragma unroll
            for (int t = 0; t < 4; ++t)
                ldsm_x4(af[t], sA + aFragOff + t * (16 * ROWSTRIDE * 4) + ks * 32);
            uint32_t bf[2][4];
#pragma unroll
            for (int p = 0; p < 2; ++p)
                ldsm_x4(bf[p], sB + bFragOff + p * (16 * ROWSTRIDE * 4) + ks * 32);
#pragma unroll
            for (int t = 0; t < 4; ++t) {
                mma_tf32(acc[t][0], af[t], bf[0][0], bf[0][1]);
                mma_tf32(acc[t][1], af[t], bf[0][2], bf[0][3]);
                mma_tf32(acc[t][2], af[t], bf[1][0], bf[1][1]);
                mma_tf32(acc[t][3], af[t], bf[1][2], bf[1][3]);
            }
        }
        __syncthreads();
    }

    const int crow = lane >> 2, ccol = (lane & 3) * 2;
#pragma unroll
    for (int t = 0; t < 4; ++t) {
        int r0 = m0 + wm * 64 + t * 16 + crow;
#pragma unroll
        for (int u = 0; u < 4; ++u) {
            int c = n0 + wn * 32 + u * 8 + ccol;
            *(float2*)(C + (size_t)r0 * Nd + c) = make_float2(acc[t][u][0], acc[t][u][1]);
            *(float2*)(C + (size_t)(r0 + 8) * Nd + c) = make_float2(acc[t][u][2], acc[t][u][3]);
        }
    }
}

// ---------------------------------------------------------------------------
// Tensor-core block-softmax attention.
// CTA: 64 queries x one (b,h). 8 warps: ms=wid>>1 (m16 slice), nh=wid&1 (n/d half).
// Per kv block (256 keys): 4 key-chunks of 64.
//   QK: Q (smem tf32) x K chunk (double-buffered smem) -> scores in regs.
//   softmax: quad-shuffle + cross-half combine (unnormalized trick).
//   PV: P -> smem (tf32); V chunk transposed to Vt[d][key]; mma accumulate O.
// O /= (bi+1+1e-6) at the end.
// smem (floats): Q[64*132] | kv0[64*132] | kv1[64*132] | Vt[128*68] | P[4*16*268] | red[256]
// ---------------------------------------------------------------------------
static constexpr int OQ = 0;
static constexpr int OKV0 = 8448;
static constexpr int OKV1 = 16896;
static constexpr int OVT = 25344;
static constexpr int OP = 34048;
static constexpr int ORED = 51200;
static constexpr int ATTN_SMEM = 51456 * 4;  // 205824 bytes

__global__ __launch_bounds__(256) void attn_mma(const float* __restrict__ Q,
                                                const float* __restrict__ K,
                                                const float* __restrict__ V,
                                                float* __restrict__ O) {
    extern __shared__ __align__(1024) float sma[];
    const uint32_t sb = smem_u32(sma);
    const int tid = threadIdx.x, lane = tid & 31, wid = tid >> 5;
    const int ms = wid >> 1, nh = wid & 1, g = lane >> 2, tig = lane & 3;
    const int qt = 31 - blockIdx.x;  // heavy tiles first
    const int h = blockIdx.y, b = blockIdx.z;
    const int q0 = qt * 64, bi = qt >> 2, sp = qt & 3;
    const size_t base = (size_t)b * Sc * Hc + (size_t)h * HDc;
    const float* Kb = K + base;
    const float* Vb = V + base;

    // per-thread chunk-copy offsets (64 rows x 32 float4)
    int goff[8];
    uint32_t soff[8];
#pragma unroll
    for (int i = 0; i < 8; ++i) {
        int id = tid + i * 256;
        int r = id >> 5, d = (id & 31) * 4;
        goff[i] = r * Hc + d;
        soff[i] = (r * 132 + d) * 4;
    }

    // Q tile -> smem (tf32)
#pragma unroll
    for (int i = 0; i < 8; ++i) {
        int id = tid + i * 256;
        int r = id >> 5, d = (id & 31) * 4;
        float4 a = *(const float4*)(Q + base + (size_t)(q0 + r) * Hc + d);
        sts4_tf32(sb + (OQ + r * 132 + d) * 4, a);
    }
    // preload K block0 chunk0
    {
        float4 rg[8];
#pragma unroll
        for (int i = 0; i < 8; ++i) rg[i] = *(const float4*)(Kb + goff[i]);
#pragma unroll
        for (int i = 0; i < 8; ++i) sts4_tf32(sb + OKV0 * 4 + soff[i], rg[i]);
    }
    __syncthreads();

    // fragment address bases
    const uint32_t aQ = sb + ((OQ + (ms * 16 + (lane & 7) + ((lane >> 3) & 1) * 8) * 132 +
                               ((lane >> 4) & 1) * 4) * 4);
    const int browk = (lane & 7) + ((lane >> 4) & 1) * 8;
    const uint32_t bcolk = ((lane >> 3) & 1) * 4;
    const uint32_t bK0 = ((nh * 32 + browk) * 132 + bcolk) * 4;
    const uint32_t bK1 = ((nh * 32 + 16 + browk) * 132 + bcolk) * 4;
    const uint32_t aP = sb + (OP + ms * 4288 + ((lane & 7) + ((lane >> 3) & 1) * 8) * 268 +
                              ((lane >> 4) & 1) * 4) * 4;
    uint32_t bV[4];
#pragma unroll
    for (int p = 0; p < 4; ++p)
        bV[p] = sb + (OVT + (nh * 64 + p * 16 + browk) * 68 + bcolk) * 4;

    float o[8][4];
#pragma unroll
    for (int u = 0; u < 8; ++u)
#pragma unroll
        for (int e = 0; e < 4; ++e) o[u][e] = 0.f;

    int cur = 0;
    const int row0 = ms * 16 + g;
    const int qi0 = q0 + row0, qi1 = qi0 + 8;

    for (int j = 0; j <= bi; ++j) {
        const int nc = (j < bi) ? 4 : (sp + 1);
        const int kb = j * BSZ;
        float s[16][4];
#pragma unroll
        for (int t = 0; t < 16; ++t)
#pragma unroll
            for (int e = 0; e < 4; ++e) s[t][e] = 0.f;

        // ---- QK chunks ----
        for (int c = 0; c < nc; ++c) {
            const float* nsrc = (c + 1 < nc) ? (Kb + (size_t)(kb + (c + 1) * 64) * Hc)
                                             : (Vb + (size_t)kb * Hc);
            float4 rg[8];
#pragma unroll
            for (int i = 0; i < 8; ++i) rg[i] = *(const float4*)(nsrc + goff[i]);

            const uint32_t bufb = sb + (cur ? OKV1 : OKV0) * 4;
#pragma unroll
            for (int ks = 0; ks < 16; ++ks) {
                uint32_t af[4];
                ldsm_x4(af, aQ + ks * 32);
                uint32_t bf[4];
                ldsm_x4(bf, bufb + bK0 + ks * 32);
                mma_tf32(s[c * 4 + 0], af, bf[0], bf[1]);
                mma_tf32(s[c * 4 + 1], af, bf[2], bf[3]);
                ldsm_x4(bf, bufb + bK1 + ks * 32);
                mma_tf32(s[c * 4 + 2], af, bf[0], bf[1]);
                mma_tf32(s[c * 4 + 3], af, bf[2], bf[3]);
            }
            const uint32_t ob = sb + (cur ? OKV0 : OKV1) * 4;
#pragma unroll
            for (int i = 0; i < 8; ++i) sts4_tf32(ob + soff[i], rg[i]);
            __syncthreads();
            cur ^= 1;
        }

        // ---- per-block softmax ----
        const bool diag = (j == bi);
        const int ntile = nc * 4;
        float mx0 = -1e30f, mx1 = -1e30f;
        for (int t = 0; t < ntile; ++t) {
            if (diag) {
                int col = kb + 64 * (t >> 2) + nh * 32 + 8 * (t & 3) + 2 * tig;
                if (col > qi0) s[t][0] = -1e30f;
                if (col + 1 > qi0) s[t][1] = -1e30f;
                if (col > qi1) s[t][2] = -1e30f;
                if (col + 1 > qi1) s[t][3] = -1e30f;
            }
            mx0 = fmaxf(mx0, fmaxf(s[t][0], s[t][1]));
            mx1 = fmaxf(mx1, fmaxf(s[t][2], s[t][3]));
        }
        mx0 = fmaxf(mx0, __shfl_xor_sync(0xffffffffu, mx0, 1));
        mx0 = fmaxf(mx0, __shfl_xor_sync(0xffffffffu, mx0, 2));
        mx1 = fmaxf(mx1, __shfl_xor_sync(0xffffffffu, mx1, 1));
        mx1 = fmaxf(mx1, __shfl_xor_sync(0xffffffffu, mx1, 2));
        float l0 = 0.f, l1 = 0.f;
        for (int t = 0; t < ntile; ++t) {
            float p0 = (s[t][0] <= -1e29f) ? 0.f : __expf(SCALE * (s[t][0] - mx0));
            float p1 = (s[t][1] <= -1e29f) ? 0.f : __expf(SCALE * (s[t][1] - mx0));
            float p2 = (s[t][2] <= -1e29f) ? 0.f : __expf(SCALE * (s[t][2] - mx1));
            float p3 = (s[t][3] <= -1e29f) ? 0.f : __expf(SCALE * (s[t][3] - mx1));
            s[t][0] = p0; s[t][1] = p1; s[t][2] = p2; s[t][3] = p3;
            l0 += p0 + p1;
            l1 += p2 + p3;
        }
        l0 += __shfl_xor_sync(0xffffffffu, l0, 1);
        l0 += __shfl_xor_sync(0xffffffffu, l0, 2);
        l1 += __shfl_xor_sync(0xffffffffu, l1, 1);
        l1 += __shfl_xor_sync(0xffffffffu, l1, 2);
        if (tig == 0) {
            sma[ORED + row0 * 2 + nh] = mx0;
            sma[ORED + 128 + row0 * 2 + nh] = l0;
            sma[ORED + (row0 + 8) * 2 + nh] = mx1;
            sma[ORED + 128 + (row0 + 8) * 2 + nh] = l1;
        }
        __syncthreads();
        {
            float mo0 = sma[ORED + row0 * 2 + (nh ^ 1)];
            float lo0 = sma[ORED + 128 + row0 * 2 + (nh ^ 1)];
            float mo1 = sma[ORED + (row0 + 8) * 2 + (nh ^ 1)];
            float lo1 = sma[ORED + 128 + (row0 + 8) * 2 + (nh ^ 1)];
            float M0 = fmaxf(mx0, mo0), M1 = fmaxf(mx1, mo1);
            float cc0 = __expf(SCALE * (mx0 - M0)), co0 = __expf(SCALE * (mo0 - M0));
            float cc1 = __expf(SCALE * (mx1 - M1)), co1 = __expf(SCALE * (mo1 - M1));
            float f0 = cc0 / (l0 * cc0 + lo0 * co0 + 1e-30f);
            float f1 = cc1 / (l1 * cc1 + lo1 * co1 + 1e-30f);
            for (int t = 0; t < ntile; ++t) {
                int col = 64 * (t >> 2) + nh * 32 + 8 * (t & 3) + 2 * tig;
                uint32_t a0 = sb + (OP + ms * 4288 + g * 268 + col) * 4;
                asm volatile("st.shared.v2.b32 [%0], {%1,%2};"
                             :: "r"(a0), "r"(f2tf32(s[t][0] * f0)),
                                "r"(f2tf32(s[t][1] * f0)) : "memory");
                asm volatile("st.shared.v2.b32 [%0], {%1,%2};"
                             :: "r"(a0 + 8 * 268 * 4), "r"(f2tf32(s[t][2] * f1)),
                                "r"(f2tf32(s[t][3] * f1)) : "memory");
            }
        }
        __syncthreads();

        // ---- PV chunks ----
        for (int c = 0; c < nc; ++c) {
            const bool have = (c + 1 < nc) || (j < bi);
            const float* nsrc = (c + 1 < nc) ? (Vb + (size_t)(kb + (c + 1) * 64) * Hc)
                                             : (Kb + (size_t)((j + 1) * BSZ) * Hc);
            float4 rg[8];
            if (have) {
#pragma unroll
                for (int i = 0; i < 8; ++i) rg[i] = *(const float4*)(nsrc + goff[i]);
            }
            const uint32_t bufb = sb + (cur ? OKV1 : OKV0) * 4;
            // transpose buf -> Vt[d][key]
#pragma unroll
            for (int i = 0; i < 8; ++i) {
                int slot = tid + i * 256;
                int d = slot & 127, kg = slot >> 7;
                uint32_t x0, x1, x2, x3;
                asm volatile("ld.shared.b32 %0, [%1];" : "=r"(x0)
                             : "r"(bufb + ((4 * kg + 0) * 132 + d) * 4));
                asm volatile("ld.shared.b32 %0, [%1];" : "=r"(x1)
                             : "r"(bufb + ((4 * kg + 1) * 132 + d) * 4));
                asm volatile("ld.shared.b32 %0, [%1];" : "=r"(x2)
                             : "r"(bufb + ((4 * kg + 2) * 132 + d) * 4));
                asm volatile("ld.shared.b32 %0, [%1];" : "=r"(x3)
                             : "r"(bufb + ((4 * kg + 3) * 132 + d) * 4));
                asm volatile("st.shared.v4.b32 [%0], {%1,%2,%3,%4};"
                             :: "r"(sb + (OVT + d * 68 + 4 * kg) * 4),
                                "r"(x0), "r"(x1), "r"(x2), "r"(x3) : "memory");
            }
            __syncthreads();
#pragma unroll
            for (int ks = 0; ks < 8; ++ks) {
                uint32_t af[4];
                ldsm_x4(af, aP + (c * 64 + ks * 8) * 4);
#pragma unroll
                for (int p = 0; p < 4; ++p) {
                    uint32_t bf[4];
                    ldsm_x4(bf, bV[p] + ks * 32);
                    mma_tf32(o[2 * p], af, bf[0], bf[1]);
                    mma_tf32(o[2 * p + 1], af, bf[2], bf[3]);
                }
            }
            if (have) {
                const uint32_t ob = sb + (cur ? OKV0 : OKV1) * 4;
#pragma unroll
                for (int i = 0; i < 8; ++i) sts4_tf32(ob + soff[i], rg[i]);
            }
            __syncthreads();
            cur ^= 1;
        }
    }

    // ---- epilogue ----
    const float invn = 1.f / ((float)(bi + 1) + 1e-6f);
#pragma unroll
    for (int u = 0; u < 8; ++u) {
        int d = nh * 64 + 16 * (u >> 1) + 8 * (u & 1) + 2 * tig;
        *(float2*)(O + base + (size_t)qi0 * Hc + d) =
            make_float2(o[u][0] * invn, o[u][1] * invn);
        *(float2*)(O + base + (size_t)qi1 * Hc + d) =
            make_float2(o[u][2] * invn, o[u][3] * invn);
    }
}

// ---------------------------------------------------------------------------
extern "C" void kernel_launch(void* const* d_in, const int* in_sizes, int n_in,
                              void* d_out, int out_size) {
    const float* hs = (const float*)d_in[0];
    const float* Wq = (const float*)d_in[1];
    const float* Wk = (const float*)d_in[2];
    const float* Wv = (const float*)d_in[3];
    const float* Wo = (const float*)d_in[4];
    float* out = (float*)d_out;

    float *qp, *kp, *vp, *aop;
    cudaGetSymbolAddress((void**)&qp, g_q);
    cudaGetSymbolAddress((void**)&kp, g_k);
    cudaGetSymbolAddress((void**)&vp, g_v);
    cudaGetSymbolAddress((void**)&aop, g_ao);

    static int smem_set = 0;
    if (!smem_set) {
        cudaFuncSetAttribute(gemm_mma, cudaFuncAttributeMaxDynamicSharedMemorySize,
                             GEMM_SMEM);
        cudaFuncSetAttribute(attn_mma, cudaFuncAttributeMaxDynamicSharedMemorySize,
                             ATTN_SMEM);
        smem_set = 1;
    }

    dim3 gg(Hc / 128, Mc / 128);  // (16, 32)
    gemm_mma<<<gg, 256, GEMM_SMEM>>>(hs, Wq, qp, Hc, Hc);
    gemm_mma<<<gg, 256, GEMM_SMEM>>>(hs, Wk, kp, Hc, Hc);
    gemm_mma<<<gg, 256, GEMM_SMEM>>>(hs, Wv, vp, Hc, Hc);

    dim3 ga(32, NHc, Bc);  // (32, 16, 2)
    attn_mma<<<ga, 256, ATTN_SMEM>>>(qp, kp, vp, aop);

    gemm_mma<<<gg, 256, GEMM_SMEM>>>(aop, Wo, out, Hc, Hc);
}

// round 5
// speedup vs baseline: 3.3862x; 1.1750x over previous
#include <cuda_runtime.h>
#include <cstdint>
#include <math.h>

// Problem constants
static constexpr int Bc = 2, Sc = 2048, Hc = 2048, NHc = 16, HDc = 128, BSZ = 256;
static constexpr int Mc = Bc * Sc;  // 4096
static constexpr float SCALE = 0.08838834764831845f;  // 1/sqrt(128)

// Scratch (device globals — no allocation allowed)
__device__ float g_q[Bc * Sc * Hc];
__device__ float g_k[Bc * Sc * Hc];
__device__ float g_v[Bc * Sc * Hc];
__device__ float g_ao[Bc * Sc * Hc];
__device__ float g_hsr[Bc * Sc * Hc];     // tf32-rounded hidden_states
__device__ float g_wr[4][Hc * Hc];        // tf32-rounded Wq,Wk,Wv,Wo

// ---------------------------------------------------------------------------
// helpers
// ---------------------------------------------------------------------------
__device__ __forceinline__ uint32_t smem_u32(const void* p) {
    uint32_t a;
    asm("{ .reg .u64 t; cvta.to.shared.u64 t, %1; cvt.u32.u64 %0, t; }"
        : "=r"(a) : "l"(p));
    return a;
}
__device__ __forceinline__ uint32_t f2tf32(float x) {
    uint32_t r;
    asm("cvt.rna.tf32.f32 %0, %1;" : "=r"(r) : "f"(x));
    return r;
}
__device__ __forceinline__ float rnd_tf32(float x) {
    return __uint_as_float(f2tf32(x));
}
__device__ __forceinline__ void ldsm_x4(uint32_t* r, uint32_t addr) {
    asm volatile("ldmatrix.sync.aligned.m8n8.x4.shared.b16 {%0,%1,%2,%3}, [%4];"
                 : "=r"(r[0]), "=r"(r[1]), "=r"(r[2]), "=r"(r[3]) : "r"(addr));
}
__device__ __forceinline__ void mma_tf32(float* d, const uint32_t* a,
                                         uint32_t b0, uint32_t b1) {
    asm volatile(
        "mma.sync.aligned.m16n8k8.row.col.f32.tf32.tf32.f32 "
        "{%0,%1,%2,%3}, {%4,%5,%6,%7}, {%8,%9}, {%0,%1,%2,%3};"
        : "+f"(d[0]), "+f"(d[1]), "+f"(d[2]), "+f"(d[3])
        : "r"(a[0]), "r"(a[1]), "r"(a[2]), "r"(a[3]), "r"(b0), "r"(b1));
}
__device__ __forceinline__ void sts4_tf32(uint32_t addr, float4 v) {
    asm volatile("st.shared.v4.b32 [%0], {%1,%2,%3,%4};"
                 :: "r"(addr), "r"(f2tf32(v.x)), "r"(f2tf32(v.y)),
                    "r"(f2tf32(v.z)), "r"(f2tf32(v.w)) : "memory");
}
__device__ __forceinline__ void cpa16(uint32_t dst, const void* src) {
    asm volatile("cp.async.cg.shared.global [%0], [%1], 16;"
                 :: "r"(dst), "l"(src) : "memory");
}
__device__ __forceinline__ void cpa_commit() {
    asm volatile("cp.async.commit_group;" ::: "memory");
}
__device__ __forceinline__ void cpa_wait1() {
    asm volatile("cp.async.wait_group 1;" ::: "memory");
}

// ---------------------------------------------------------------------------
// tf32 pre-rounding pass (elementwise, float4)
// ---------------------------------------------------------------------------
__global__ __launch_bounds__(256) void round_k(const float* __restrict__ in,
                                               float* __restrict__ out, int n4) {
    int i = blockIdx.x * blockDim.x + threadIdx.x;
    if (i < n4) {
        float4 v = ((const float4*)in)[i];
        float4 r;
        r.x = rnd_tf32(v.x); r.y = rnd_tf32(v.y);
        r.z = rnd_tf32(v.z); r.w = rnd_tf32(v.w);
        ((float4*)out)[i] = r;
    }
}

// ---------------------------------------------------------------------------
// tf32 mma.sync GEMM, cp.async 3-stage pipeline.
// Inputs MUST be pre-rounded to tf32 (HW truncation then == cvt.rna).
// CTA tile 128x128, BK=32, 256 threads (8 warps, 2x4), warp tile 64x32.
// ---------------------------------------------------------------------------
static constexpr int RSF = 36;                     // row stride in floats
static constexpr int ATILE = 128 * RSF * 4;        // 18432 bytes
static constexpr int STAGE = 2 * ATILE;            // 36864 bytes (A+B)
static constexpr int GEMM_SMEM = 3 * STAGE;        // 110592 bytes

__global__ __launch_bounds__(256, 2) void gemm_mma(const float* __restrict__ A,
                                                   const float* __restrict__ W,
                                                   float* __restrict__ C,
                                                   int Kd, int Nd) {
    extern __shared__ __align__(128) char smem[];
    const uint32_t sb = smem_u32(smem);
    const int tid = threadIdx.x;
    const int lane = tid & 31, wid = tid >> 5;
    const int wm = wid >> 2, wn = wid & 3;
    const int m0 = blockIdx.y * 128, n0 = blockIdx.x * 128;
    const int NKB = Kd / 32;

    const float* gA[4];
    const float* gB[4];
    uint32_t so[4];
#pragma unroll
    for (int i = 0; i < 4; ++i) {
        int id = tid + i * 256;
        int row = id >> 3, ch = id & 7;
        gA[i] = A + (size_t)(m0 + row) * Kd + ch * 4;
        gB[i] = W + (size_t)(n0 + row) * Kd + ch * 4;
        so[i] = row * (RSF * 4) + ch * 16;
    }

    const int arow = wm * 64 + (lane & 7) + ((lane >> 3) & 1) * 8;
    const int acol = ((lane >> 4) & 1) * 4;
    const uint32_t aFragOff = arow * (RSF * 4) + acol * 4;
    const int brow = wn * 32 + (lane & 7) + ((lane >> 4) & 1) * 8;
    const int bcol = ((lane >> 3) & 1) * 4;
    const uint32_t bFragOff = brow * (RSF * 4) + bcol * 4;

    float acc[4][4][4];
#pragma unroll
    for (int t = 0; t < 4; ++t)
#pragma unroll
        for (int u = 0; u < 4; ++u)
#pragma unroll
            for (int e = 0; e < 4; ++e) acc[t][u][e] = 0.f;

    // prologue: stages 0 and 1
#pragma unroll
    for (int s = 0; s < 2; ++s) {
        const uint32_t st = sb + s * STAGE;
#pragma unroll
        for (int i = 0; i < 4; ++i) {
            cpa16(st + so[i], gA[i] + s * 32);
            cpa16(st + ATILE + so[i], gB[i] + s * 32);
        }
        cpa_commit();
    }

    int stage = 0;  // stage index of kb in the 3-ring
    for (int kb = 0; kb < NKB; ++kb) {
        cpa_wait1();
        __syncthreads();
        // issue kb+2 into ring slot (stage+2)%3
        {
            int ns = stage + 2;
            if (ns >= 3) ns -= 3;
            if (kb + 2 < NKB) {
                const uint32_t st = sb + ns * STAGE;
#pragma unroll
                for (int i = 0; i < 4; ++i) {
                    cpa16(st + so[i], gA[i] + (kb + 2) * 32);
                    cpa16(st + ATILE + so[i], gB[i] + (kb + 2) * 32);
                }
            }
            cpa_commit();
        }
        const uint32_t sA = sb + stage * STAGE;
        const uint32_t sB = sA + ATILE;
#pragma unroll
        for (int ks = 0; ks < 4; ++ks) {
            uint32_t af[4][4];
#pragma unroll
            for (int t = 0; t < 4; ++t)
                ldsm_x4(af[t], sA + aFragOff + t * (16 * RSF * 4) + ks * 32);
            uint32_t bf[2][4];
#pragma unroll
            for (int p = 0; p < 2; ++p)
                ldsm_x4(bf[p], sB + bFragOff + p * (16 * RSF * 4) + ks * 32);
#pragma unroll
            for (int t = 0; t < 4; ++t) {
                mma_tf32(acc[t][0], af[t], bf[0][0], bf[0][1]);
                mma_tf32(acc[t][1], af[t], bf[0][2], bf[0][3]);
                mma_tf32(acc[t][2], af[t], bf[1][0], bf[1][1]);
                mma_tf32(acc[t][3], af[t], bf[1][2], bf[1][3]);
            }
        }
        if (++stage == 3) stage = 0;
    }

    const int crow = lane >> 2, ccol = (lane & 3) * 2;
#pragma unroll
    for (int t = 0; t < 4; ++t) {
        int r0 = m0 + wm * 64 + t * 16 + crow;
#pragma unroll
        for (int u = 0; u < 4; ++u) {
            int c = n0 + wn * 32 + u * 8 + ccol;
            *(float2*)(C + (size_t)r0 * Nd + c) = make_float2(acc[t][u][0], acc[t][u][1]);
            *(float2*)(C + (size_t)(r0 + 8) * Nd + c) = make_float2(acc[t][u][2], acc[t][u][3]);
        }
    }
}

// ---------------------------------------------------------------------------
// Tensor-core block-softmax attention (R4, validated). Epilogue now emits
// tf32-rounded output so the Wo GEMM can consume raw bits.
// ---------------------------------------------------------------------------
static constexpr int OQ = 0;
static constexpr int OKV0 = 8448;
static constexpr int OKV1 = 16896;
static constexpr int OVT = 25344;
static constexpr int OP = 34048;
static constexpr int ORED = 51200;
static constexpr int ATTN_SMEM = 51456 * 4;  // 205824 bytes

__global__ __launch_bounds__(256) void attn_mma(const float* __restrict__ Q,
                                                const float* __restrict__ K,
                                                const float* __restrict__ V,
                                                float* __restrict__ O) {
    extern __shared__ __align__(1024) float sma[];
    const uint32_t sb = smem_u32(sma);
    const int tid = threadIdx.x, lane = tid & 31, wid = tid >> 5;
    const int ms = wid >> 1, nh = wid & 1, g = lane >> 2, tig = lane & 3;
    const int qt = 31 - blockIdx.x;  // heavy tiles first
    const int h = blockIdx.y, b = blockIdx.z;
    const int q0 = qt * 64, bi = qt >> 2, sp = qt & 3;
    const size_t base = (size_t)b * Sc * Hc + (size_t)h * HDc;
    const float* Kb = K + base;
    const float* Vb = V + base;

    int goff[8];
    uint32_t soff[8];
#pragma unroll
    for (int i = 0; i < 8; ++i) {
        int id = tid + i * 256;
        int r = id >> 5, d = (id & 31) * 4;
        goff[i] = r * Hc + d;
        soff[i] = (r * 132 + d) * 4;
    }

#pragma unroll
    for (int i = 0; i < 8; ++i) {
        int id = tid + i * 256;
        int r = id >> 5, d = (id & 31) * 4;
        float4 a = *(const float4*)(Q + base + (size_t)(q0 + r) * Hc + d);
        sts4_tf32(sb + (OQ + r * 132 + d) * 4, a);
    }
    {
        float4 rg[8];
#pragma unroll
        for (int i = 0; i < 8; ++i) rg[i] = *(const float4*)(Kb + goff[i]);
#pragma unroll
        for (int i = 0; i < 8; ++i) sts4_tf32(sb + OKV0 * 4 + soff[i], rg[i]);
    }
    __syncthreads();

    const uint32_t aQ = sb + ((OQ + (ms * 16 + (lane & 7) + ((lane >> 3) & 1) * 8) * 132 +
                               ((lane >> 4) & 1) * 4) * 4);
    const int browk = (lane & 7) + ((lane >> 4) & 1) * 8;
    const uint32_t bcolk = ((lane >> 3) & 1) * 4;
    const uint32_t bK0 = ((nh * 32 + browk) * 132 + bcolk) * 4;
    const uint32_t bK1 = ((nh * 32 + 16 + browk) * 132 + bcolk) * 4;
    const uint32_t aP = sb + (OP + ms * 4288 + ((lane & 7) + ((lane >> 3) & 1) * 8) * 268 +
                              ((lane >> 4) & 1) * 4) * 4;
    uint32_t bV[4];
#pragma unroll
    for (int p = 0; p < 4; ++p)
        bV[p] = sb + (OVT + (nh * 64 + p * 16 + browk) * 68 + bcolk) * 4;

    float o[8][4];
#pragma unroll
    for (int u = 0; u < 8; ++u)
#pragma unroll
        for (int e = 0; e < 4; ++e) o[u][e] = 0.f;

    int cur = 0;
    const int row0 = ms * 16 + g;
    const int qi0 = q0 + row0, qi1 = qi0 + 8;

    for (int j = 0; j <= bi; ++j) {
        const int nc = (j < bi) ? 4 : (sp + 1);
        const int kb = j * BSZ;
        float s[16][4];
#pragma unroll
        for (int t = 0; t < 16; ++t)
#pragma unroll
            for (int e = 0; e < 4; ++e) s[t][e] = 0.f;

        for (int c = 0; c < nc; ++c) {
            const float* nsrc = (c + 1 < nc) ? (Kb + (size_t)(kb + (c + 1) * 64) * Hc)
                                             : (Vb + (size_t)kb * Hc);
            float4 rg[8];
#pragma unroll
            for (int i = 0; i < 8; ++i) rg[i] = *(const float4*)(nsrc + goff[i]);

            const uint32_t bufb = sb + (cur ? OKV1 : OKV0) * 4;
#pragma unroll
            for (int ks = 0; ks < 16; ++ks) {
                uint32_t af[4];
                ldsm_x4(af, aQ + ks * 32);
                uint32_t bf[4];
                ldsm_x4(bf, bufb + bK0 + ks * 32);
                mma_tf32(s[c * 4 + 0], af, bf[0], bf[1]);
                mma_tf32(s[c * 4 + 1], af, bf[2], bf[3]);
                ldsm_x4(bf, bufb + bK1 + ks * 32);
                mma_tf32(s[c * 4 + 2], af, bf[0], bf[1]);
                mma_tf32(s[c * 4 + 3], af, bf[2], bf[3]);
            }
            const uint32_t ob = sb + (cur ? OKV0 : OKV1) * 4;
#pragma unroll
            for (int i = 0; i < 8; ++i) sts4_tf32(ob + soff[i], rg[i]);
            __syncthreads();
            cur ^= 1;
        }

        const bool diag = (j == bi);
        const int ntile = nc * 4;
        float mx0 = -1e30f, mx1 = -1e30f;
        for (int t = 0; t < ntile; ++t) {
            if (diag) {
                int col = kb + 64 * (t >> 2) + nh * 32 + 8 * (t & 3) + 2 * tig;
                if (col > qi0) s[t][0] = -1e30f;
                if (col + 1 > qi0) s[t][1] = -1e30f;
                if (col > qi1) s[t][2] = -1e30f;
                if (col + 1 > qi1) s[t][3] = -1e30f;
            }
            mx0 = fmaxf(mx0, fmaxf(s[t][0], s[t][1]));
            mx1 = fmaxf(mx1, fmaxf(s[t][2], s[t][3]));
        }
        mx0 = fmaxf(mx0, __shfl_xor_sync(0xffffffffu, mx0, 1));
        mx0 = fmaxf(mx0, __shfl_xor_sync(0xffffffffu, mx0, 2));
        mx1 = fmaxf(mx1, __shfl_xor_sync(0xffffffffu, mx1, 1));
        mx1 = fmaxf(mx1, __shfl_xor_sync(0xffffffffu, mx1, 2));
        float l0 = 0.f, l1 = 0.f;
        for (int t = 0; t < ntile; ++t) {
            float p0 = (s[t][0] <= -1e29f) ? 0.f : __expf(SCALE * (s[t][0] - mx0));
            float p1 = (s[t][1] <= -1e29f) ? 0.f : __expf(SCALE * (s[t][1] - mx0));
            float p2 = (s[t][2] <= -1e29f) ? 0.f : __expf(SCALE * (s[t][2] - mx1));
            float p3 = (s[t][3] <= -1e29f) ? 0.f : __expf(SCALE * (s[t][3] - mx1));
            s[t][0] = p0; s[t][1] = p1; s[t][2] = p2; s[t][3] = p3;
            l0 += p0 + p1;
            l1 += p2 + p3;
        }
        l0 += __shfl_xor_sync(0xffffffffu, l0, 1);
        l0 += __shfl_xor_sync(0xffffffffu, l0, 2);
        l1 += __shfl_xor_sync(0xffffffffu, l1, 1);
        l1 += __shfl_xor_sync(0xffffffffu, l1, 2);
        if (tig == 0) {
            sma[ORED + row0 * 2 + nh] = mx0;
            sma[ORED + 128 + row0 * 2 + nh] = l0;
            sma[ORED + (row0 + 8) * 2 + nh] = mx1;
            sma[ORED + 128 + (row0 + 8) * 2 + nh] = l1;
        }
        __syncthreads();
        {
            float mo0 = sma[ORED + row0 * 2 + (nh ^ 1)];
            float lo0 = sma[ORED + 128 + row0 * 2 + (nh ^ 1)];
            float mo1 = sma[ORED + (row0 + 8) * 2 + (nh ^ 1)];
            float lo1 = sma[ORED + 128 + (row0 + 8) * 2 + (nh ^ 1)];
            float M0 = fmaxf(mx0, mo0), M1 = fmaxf(mx1, mo1);
            float cc0 = __expf(SCALE * (mx0 - M0)), co0 = __expf(SCALE * (mo0 - M0));
            float cc1 = __expf(SCALE * (mx1 - M1)), co1 = __expf(SCALE * (mo1 - M1));
            float f0 = cc0 / (l0 * cc0 + lo0 * co0 + 1e-30f);
            float f1 = cc1 / (l1 * cc1 + lo1 * co1 + 1e-30f);
            for (int t = 0; t < ntile; ++t) {
                int col = 64 * (t >> 2) + nh * 32 + 8 * (t & 3) + 2 * tig;
                uint32_t a0 = sb + (OP + ms * 4288 + g * 268 + col) * 4;
                asm volatile("st.shared.v2.b32 [%0], {%1,%2};"
                             :: "r"(a0), "r"(f2tf32(s[t][0] * f0)),
                                "r"(f2tf32(s[t][1] * f0)) : "memory");
                asm volatile("st.shared.v2.b32 [%0], {%1,%2};"
                             :: "r"(a0 + 8 * 268 * 4), "r"(f2tf32(s[t][2] * f1)),
                                "r"(f2tf32(s[t][3] * f1)) : "memory");
            }
        }
        __syncthreads();

        for (int c = 0; c < nc; ++c) {
            const bool have = (c + 1 < nc) || (j < bi);
            const float* nsrc = (c + 1 < nc) ? (Vb + (size_t)(kb + (c + 1) * 64) * Hc)
                                             : (Kb + (size_t)((j + 1) * BSZ) * Hc);
            float4 rg[8];
            if (have) {
#pragma unroll
                for (int i = 0; i < 8; ++i) rg[i] = *(const float4*)(nsrc + goff[i]);
            }
            const uint32_t bufb = sb + (cur ? OKV1 : OKV0) * 4;
#pragma unroll
            for (int i = 0; i < 8; ++i) {
                int slot = tid + i * 256;
                int d = slot & 127, kg = slot >> 7;
                uint32_t x0, x1, x2, x3;
                asm volatile("ld.shared.b32 %0, [%1];" : "=r"(x0)
                             : "r"(bufb + ((4 * kg + 0) * 132 + d) * 4));
                asm volatile("ld.shared.b32 %0, [%1];" : "=r"(x1)
                             : "r"(bufb + ((4 * kg + 1) * 132 + d) * 4));
                asm volatile("ld.shared.b32 %0, [%1];" : "=r"(x2)
                             : "r"(bufb + ((4 * kg + 2) * 132 + d) * 4));
                asm volatile("ld.shared.b32 %0, [%1];" : "=r"(x3)
                             : "r"(bufb + ((4 * kg + 3) * 132 + d) * 4));
                asm volatile("st.shared.v4.b32 [%0], {%1,%2,%3,%4};"
                             :: "r"(sb + (OVT + d * 68 + 4 * kg) * 4),
                                "r"(x0), "r"(x1), "r"(x2), "r"(x3) : "memory");
            }
            __syncthreads();
#pragma unroll
            for (int ks = 0; ks < 8; ++ks) {
                uint32_t af[4];
                ldsm_x4(af, aP + (c * 64 + ks * 8) * 4);
#pragma unroll
                for (int p = 0; p < 4; ++p) {
                    uint32_t bf[4];
                    ldsm_x4(bf, bV[p] + ks * 32);
                    mma_tf32(o[2 * p], af, bf[0], bf[1]);
                    mma_tf32(o[2 * p + 1], af, bf[2], bf[3]);
                }
            }
            if (have) {
                const uint32_t ob = sb + (cur ? OKV0 : OKV1) * 4;
#pragma unroll
                for (int i = 0; i < 8; ++i) sts4_tf32(ob + soff[i], rg[i]);
            }
            __syncthreads();
            cur ^= 1;
        }
    }

    // epilogue: tf32-rounded output (feeds raw-bit Wo GEMM)
    const float invn = 1.f / ((float)(bi + 1) + 1e-6f);
#pragma unroll
    for (int u = 0; u < 8; ++u) {
        int d = nh * 64 + 16 * (u >> 1) + 8 * (u & 1) + 2 * tig;
        *(float2*)(O + base + (size_t)qi0 * Hc + d) =
            make_float2(rnd_tf32(o[u][0] * invn), rnd_tf32(o[u][1] * invn));
        *(float2*)(O + base + (size_t)qi1 * Hc + d) =
            make_float2(rnd_tf32(o[u][2] * invn), rnd_tf32(o[u][3] * invn));
    }
}

// ---------------------------------------------------------------------------
extern "C" void kernel_launch(void* const* d_in, const int* in_sizes, int n_in,
                              void* d_out, int out_size) {
    const float* hs = (const float*)d_in[0];
    const float* Wq = (const float*)d_in[1];
    const float* Wk = (const float*)d_in[2];
    const float* Wv = (const float*)d_in[3];
    const float* Wo = (const float*)d_in[4];
    float* out = (float*)d_out;

    float *qp, *kp, *vp, *aop, *hsr, *wr;
    cudaGetSymbolAddress((void**)&qp, g_q);
    cudaGetSymbolAddress((void**)&kp, g_k);
    cudaGetSymbolAddress((void**)&vp, g_v);
    cudaGetSymbolAddress((void**)&aop, g_ao);
    cudaGetSymbolAddress((void**)&hsr, g_hsr);
    cudaGetSymbolAddress((void**)&wr, g_wr);
    float* wqr = wr;
    float* wkr = wr + (size_t)Hc * Hc;
    float* wvr = wr + 2 * (size_t)Hc * Hc;
    float* wor = wr + 3 * (size_t)Hc * Hc;

    static int smem_set = 0;
    if (!smem_set) {
        cudaFuncSetAttribute(gemm_mma, cudaFuncAttributeMaxDynamicSharedMemorySize,
                             GEMM_SMEM);
        cudaFuncSetAttribute(attn_mma, cudaFuncAttributeMaxDynamicSharedMemorySize,
                             ATTN_SMEM);
        smem_set = 1;
    }

    // tf32 pre-rounding
    const int nHS4 = Bc * Sc * Hc / 4;   // 2M
    const int nW4 = Hc * Hc / 4;         // 1M
    round_k<<<nHS4 / 256, 256>>>(hs, hsr, nHS4);
    round_k<<<nW4 / 256, 256>>>(Wq, wqr, nW4);
    round_k<<<nW4 / 256, 256>>>(Wk, wkr, nW4);
    round_k<<<nW4 / 256, 256>>>(Wv, wvr, nW4);
    round_k<<<nW4 / 256, 256>>>(Wo, wor, nW4);

    dim3 gg(Hc / 128, Mc / 128);  // (16, 32)
    gemm_mma<<<gg, 256, GEMM_SMEM>>>(hsr, wqr, qp, Hc, Hc);
    gemm_mma<<<gg, 256, GEMM_SMEM>>>(hsr, wkr, kp, Hc, Hc);
    gemm_mma<<<gg, 256, GEMM_SMEM>>>(hsr, wvr, vp, Hc, Hc);

    dim3 ga(32, NHc, Bc);  // (32, 16, 2)
    attn_mma<<<ga, 256, ATTN_SMEM>>>(qp, kp, vp, aop);

    gemm_mma<<<gg, 256, GEMM_SMEM>>>(aop, wor, out, Hc, Hc);
}

// round 6
// speedup vs baseline: 3.5757x; 1.0560x over previous
#include <cuda_runtime.h>
#include <cstdint>
#include <math.h>

// Problem constants
static constexpr int Bc = 2, Sc = 2048, Hc = 2048, NHc = 16, HDc = 128, BSZ = 256;
static constexpr int Mc = Bc * Sc;  // 4096
static constexpr float SCALE = 0.08838834764831845f;  // 1/sqrt(128)

// Scratch (device globals — no allocation allowed)
__device__ float g_q[Bc * Sc * Hc];
__device__ float g_k[Bc * Sc * Hc];
__device__ float g_vt[Bc * Sc * Hc];      // V transposed: [b, h, d, s]
__device__ float g_ao[Bc * Sc * Hc];
__device__ float g_hsr[Bc * Sc * Hc];     // tf32-rounded hidden_states
__device__ float g_wr[4][Hc * Hc];        // tf32-rounded Wq,Wk,Wv,Wo

// ---------------------------------------------------------------------------
// helpers
// ---------------------------------------------------------------------------
__device__ __forceinline__ uint32_t smem_u32(const void* p) {
    uint32_t a;
    asm("{ .reg .u64 t; cvta.to.shared.u64 t, %1; cvt.u32.u64 %0, t; }"
        : "=r"(a) : "l"(p));
    return a;
}
__device__ __forceinline__ uint32_t f2tf32(float x) {
    uint32_t r;
    asm("cvt.rna.tf32.f32 %0, %1;" : "=r"(r) : "f"(x));
    return r;
}
__device__ __forceinline__ float rnd_tf32(float x) {
    return __uint_as_float(f2tf32(x));
}
__device__ __forceinline__ void ldsm_x4(uint32_t* r, uint32_t addr) {
    asm volatile("ldmatrix.sync.aligned.m8n8.x4.shared.b16 {%0,%1,%2,%3}, [%4];"
                 : "=r"(r[0]), "=r"(r[1]), "=r"(r[2]), "=r"(r[3]) : "r"(addr));
}
__device__ __forceinline__ void mma_tf32(float* d, const uint32_t* a,
                                         uint32_t b0, uint32_t b1) {
    asm volatile(
        "mma.sync.aligned.m16n8k8.row.col.f32.tf32.tf32.f32 "
        "{%0,%1,%2,%3}, {%4,%5,%6,%7}, {%8,%9}, {%0,%1,%2,%3};"
        : "+f"(d[0]), "+f"(d[1]), "+f"(d[2]), "+f"(d[3])
        : "r"(a[0]), "r"(a[1]), "r"(a[2]), "r"(a[3]), "r"(b0), "r"(b1));
}
__device__ __forceinline__ void cpa16(uint32_t dst, const void* src) {
    asm volatile("cp.async.cg.shared.global [%0], [%1], 16;"
                 :: "r"(dst), "l"(src) : "memory");
}
__device__ __forceinline__ void cpa_commit() {
    asm volatile("cp.async.commit_group;" ::: "memory");
}
__device__ __forceinline__ void cpa_wait1() {
    asm volatile("cp.async.wait_group 1;" ::: "memory");
}
__device__ __forceinline__ void cpa_wait0() {
    asm volatile("cp.async.wait_group 0;" ::: "memory");
}

// ---------------------------------------------------------------------------
// tf32 pre-rounding pass (elementwise, float4)
// ---------------------------------------------------------------------------
__global__ __launch_bounds__(256) void round_k(const float* __restrict__ in,
                                               float* __restrict__ out, int n4) {
    int i = blockIdx.x * blockDim.x + threadIdx.x;
    if (i < n4) {
        float4 v = ((const float4*)in)[i];
        float4 r;
        r.x = rnd_tf32(v.x); r.y = rnd_tf32(v.y);
        r.z = rnd_tf32(v.z); r.w = rnd_tf32(v.w);
        ((float4*)out)[i] = r;
    }
}

// ---------------------------------------------------------------------------
// tf32 mma.sync GEMM, cp.async 3-stage pipeline.
// mode 0: plain fp32 output (final Wo GEMM)
// mode 1: tf32-rounded output (Q, K projections)
// mode 2: tf32-rounded output written TRANSPOSED per head: [b,h,d,s] (V proj)
// ---------------------------------------------------------------------------
static constexpr int RSF = 36;
static constexpr int ATILE = 128 * RSF * 4;        // 18432 bytes
static constexpr int STAGE = 2 * ATILE;            // 36864 bytes (A+B)
static constexpr int GEMM_SMEM = 3 * STAGE;        // 110592 bytes

__global__ __launch_bounds__(256, 2) void gemm_mma(const float* __restrict__ A,
                                                   const float* __restrict__ W,
                                                   float* __restrict__ C,
                                                   int Kd, int Nd, int mode) {
    extern __shared__ __align__(128) char smem[];
    const uint32_t sb = smem_u32(smem);
    const int tid = threadIdx.x;
    const int lane = tid & 31, wid = tid >> 5;
    const int wm = wid >> 2, wn = wid & 3;
    const int m0 = blockIdx.y * 128, n0 = blockIdx.x * 128;
    const int NKB = Kd / 32;

    const float* gA[4];
    const float* gB[4];
    uint32_t so[4];
#pragma unroll
    for (int i = 0; i < 4; ++i) {
        int id = tid + i * 256;
        int row = id >> 3, ch = id & 7;
        gA[i] = A + (size_t)(m0 + row) * Kd + ch * 4;
        gB[i] = W + (size_t)(n0 + row) * Kd + ch * 4;
        so[i] = row * (RSF * 4) + ch * 16;
    }

    const int arow = wm * 64 + (lane & 7) + ((lane >> 3) & 1) * 8;
    const int acol = ((lane >> 4) & 1) * 4;
    const uint32_t aFragOff = arow * (RSF * 4) + acol * 4;
    const int brow = wn * 32 + (lane & 7) + ((lane >> 4) & 1) * 8;
    const int bcol = ((lane >> 3) & 1) * 4;
    const uint32_t bFragOff = brow * (RSF * 4) + bcol * 4;

    float acc[4][4][4];
#pragma unroll
    for (int t = 0; t < 4; ++t)
#pragma unroll
        for (int u = 0; u < 4; ++u)
#pragma unroll
            for (int e = 0; e < 4; ++e) acc[t][u][e] = 0.f;

#pragma unroll
    for (int s = 0; s < 2; ++s) {
        const uint32_t st = sb + s * STAGE;
#pragma unroll
        for (int i = 0; i < 4; ++i) {
            cpa16(st + so[i], gA[i] + s * 32);
            cpa16(st + ATILE + so[i], gB[i] + s * 32);
        }
        cpa_commit();
    }

    int stage = 0;
    for (int kb = 0; kb < NKB; ++kb) {
        cpa_wait1();
        __syncthreads();
        {
            int ns = stage + 2;
            if (ns >= 3) ns -= 3;
            if (kb + 2 < NKB) {
                const uint32_t st = sb + ns * STAGE;
#pragma unroll
                for (int i = 0; i < 4; ++i) {
                    cpa16(st + so[i], gA[i] + (kb + 2) * 32);
                    cpa16(st + ATILE + so[i], gB[i] + (kb + 2) * 32);
                }
            }
            cpa_commit();
        }
        const uint32_t sA = sb + stage * STAGE;
        const uint32_t sB = sA + ATILE;
#pragma unroll
        for (int ks = 0; ks < 4; ++ks) {
            uint32_t af[4][4];
#pragma unroll
            for (int t = 0; t < 4; ++t)
                ldsm_x4(af[t], sA + aFragOff + t * (16 * RSF * 4) + ks * 32);
            uint32_t bf[2][4];
#pragma unroll
            for (int p = 0; p < 2; ++p)
                ldsm_x4(bf[p], sB + bFragOff + p * (16 * RSF * 4) + ks * 32);
#pragma unroll
            for (int t = 0; t < 4; ++t) {
                mma_tf32(acc[t][0], af[t], bf[0][0], bf[0][1]);
                mma_tf32(acc[t][1], af[t], bf[0][2], bf[0][3]);
                mma_tf32(acc[t][2], af[t], bf[1][0], bf[1][1]);
                mma_tf32(acc[t][3], af[t], bf[1][2], bf[1][3]);
            }
        }
        if (++stage == 3) stage = 0;
    }

    const int crow = lane >> 2, ccol = (lane & 3) * 2;
    if (mode == 2) {
        // transposed per-head V output: C[((b*NH+h)*HD+d)*S + s]
#pragma unroll
        for (int t = 0; t < 4; ++t) {
            int r0 = m0 + wm * 64 + t * 16 + crow;
#pragma unroll
            for (int u = 0; u < 4; ++u) {
                int c = n0 + wn * 32 + u * 8 + ccol;
#pragma unroll
                for (int e = 0; e < 4; ++e) {
                    int r = r0 + (e >> 1) * 8;
                    int cc = c + (e & 1);
                    int bq = r >> 11, s = r & 2047;
                    int hh = cc >> 7, d = cc & 127;
                    C[(((size_t)bq * NHc + hh) * HDc + d) * Sc + s] = rnd_tf32(acc[t][u][e]);
                }
            }
        }
    } else if (mode == 1) {
#pragma unroll
        for (int t = 0; t < 4; ++t) {
            int r0 = m0 + wm * 64 + t * 16 + crow;
#pragma unroll
            for (int u = 0; u < 4; ++u) {
                int c = n0 + wn * 32 + u * 8 + ccol;
                *(float2*)(C + (size_t)r0 * Nd + c) =
                    make_float2(rnd_tf32(acc[t][u][0]), rnd_tf32(acc[t][u][1]));
                *(float2*)(C + (size_t)(r0 + 8) * Nd + c) =
                    make_float2(rnd_tf32(acc[t][u][2]), rnd_tf32(acc[t][u][3]));
            }
        }
    } else {
#pragma unroll
        for (int t = 0; t < 4; ++t) {
            int r0 = m0 + wm * 64 + t * 16 + crow;
#pragma unroll
            for (int u = 0; u < 4; ++u) {
                int c = n0 + wn * 32 + u * 8 + ccol;
                *(float2*)(C + (size_t)r0 * Nd + c) = make_float2(acc[t][u][0], acc[t][u][1]);
                *(float2*)(C + (size_t)(r0 + 8) * Nd + c) = make_float2(acc[t][u][2], acc[t][u][3]);
            }
        }
    }
}

// ---------------------------------------------------------------------------
// Tensor-core block-softmax attention, cp.async edition.
// Inputs pre-rounded to tf32 by the projection GEMMs; V pre-transposed [b,h,d,s].
// smem (floats): Q[64*132]=8448 | buf0[8704] | buf1[8704] | P[4*4288] | red[256]
// ---------------------------------------------------------------------------
static constexpr int AQ = 0;
static constexpr int AB0 = 8448;
static constexpr int AB1 = 17152;
static constexpr int AP = 25856;
static constexpr int ARED = 43008;
static constexpr int ATTN_SMEM = 43264 * 4;  // 173056 bytes

__global__ __launch_bounds__(256) void attn_mma(const float* __restrict__ Q,
                                                const float* __restrict__ K,
                                                const float* __restrict__ Vt,
                                                float* __restrict__ O) {
    extern __shared__ __align__(1024) float sma[];
    const uint32_t sb = smem_u32(sma);
    const int tid = threadIdx.x, lane = tid & 31, wid = tid >> 5;
    const int ms = wid >> 1, nh = wid & 1, g = lane >> 2, tig = lane & 3;
    const int qt = 31 - blockIdx.x;  // heavy tiles first
    const int h = blockIdx.y, b = blockIdx.z;
    const int q0 = qt * 64, bi = qt >> 2, sp = qt & 3;
    const size_t base = (size_t)b * Sc * Hc + (size_t)h * HDc;
    const float* Kb = K + base;
    const float* Qb = Q + base;
    const float* Vtb = Vt + ((size_t)(b * NHc + h) * HDc) * Sc;

    // cp.async slot geometry
    int k_r[8], k_c[8];
    uint32_t k_do[8];
    int v_r[8], v_c[8];
    uint32_t v_do[8];
#pragma unroll
    for (int i = 0; i < 8; ++i) {
        int id = tid + i * 256;
        k_r[i] = id >> 5;
        k_c[i] = (id & 31) * 4;
        k_do[i] = (uint32_t)(k_r[i] * 132 + k_c[i]) * 4;
        v_r[i] = id >> 4;
        v_c[i] = (id & 15) * 4;
        v_do[i] = (uint32_t)(v_r[i] * 68 + v_c[i]) * 4;
    }

    // prologue: Q tile + K block0 chunk0 (one group)
#pragma unroll
    for (int i = 0; i < 8; ++i)
        cpa16(sb + AQ * 4 + k_do[i], Qb + (size_t)(q0 + k_r[i]) * Hc + k_c[i]);
#pragma unroll
    for (int i = 0; i < 8; ++i)
        cpa16(sb + AB0 * 4 + k_do[i], Kb + (size_t)k_r[i] * Hc + k_c[i]);
    cpa_commit();

    // fragment address bases
    const uint32_t aQ = sb + ((AQ + (ms * 16 + (lane & 7) + ((lane >> 3) & 1) * 8) * 132 +
                               ((lane >> 4) & 1) * 4) * 4);
    const int browk = (lane & 7) + ((lane >> 4) & 1) * 8;
    const uint32_t bcolk = ((lane >> 3) & 1) * 4;
    const uint32_t bK0 = ((nh * 32 + browk) * 132 + bcolk) * 4;
    const uint32_t bK1 = ((nh * 32 + 16 + browk) * 132 + bcolk) * 4;
    const uint32_t aP = sb + (AP + ms * 4288 + ((lane & 7) + ((lane >> 3) & 1) * 8) * 268 +
                              ((lane >> 4) & 1) * 4) * 4;
    uint32_t bVo[4];
#pragma unroll
    for (int p = 0; p < 4; ++p)
        bVo[p] = ((nh * 64 + p * 16 + browk) * 68 + bcolk) * 4;

    float o[8][4];
#pragma unroll
    for (int u = 0; u < 8; ++u)
#pragma unroll
        for (int e = 0; e < 4; ++e) o[u][e] = 0.f;

    int cur = 0;
    const int row0 = ms * 16 + g;
    const int qi0 = q0 + row0, qi1 = qi0 + 8;

    for (int j = 0; j <= bi; ++j) {
        const int nc = (j < bi) ? 4 : (sp + 1);
        const int kb = j * BSZ;
        float s[16][4];
#pragma unroll
        for (int t = 0; t < 16; ++t)
#pragma unroll
            for (int e = 0; e < 4; ++e) s[t][e] = 0.f;

        // ---- QK chunks ----
        for (int c = 0; c < nc; ++c) {
            cpa_wait0();
            __syncthreads();
            // prefetch next into the other buffer
            const uint32_t nb = sb + (cur ? AB0 : AB1) * 4;
            if (c + 1 < nc) {
                const int ka = kb + (c + 1) * 64;
#pragma unroll
                for (int i = 0; i < 8; ++i)
                    cpa16(nb + k_do[i], Kb + (size_t)(ka + k_r[i]) * Hc + k_c[i]);
            } else {
#pragma unroll
                for (int i = 0; i < 8; ++i)
                    cpa16(nb + v_do[i], Vtb + (size_t)v_r[i] * Sc + kb + v_c[i]);
            }
            cpa_commit();

            const uint32_t bufb = sb + (cur ? AB1 : AB0) * 4;
#pragma unroll
            for (int ks = 0; ks < 16; ++ks) {
                uint32_t af[4];
                ldsm_x4(af, aQ + ks * 32);
                uint32_t bf[4];
                ldsm_x4(bf, bufb + bK0 + ks * 32);
                mma_tf32(s[c * 4 + 0], af, bf[0], bf[1]);
                mma_tf32(s[c * 4 + 1], af, bf[2], bf[3]);
                ldsm_x4(bf, bufb + bK1 + ks * 32);
                mma_tf32(s[c * 4 + 2], af, bf[0], bf[1]);
                mma_tf32(s[c * 4 + 3], af, bf[2], bf[3]);
            }
            cur ^= 1;
        }

        // ---- per-block softmax ----
        const bool diag = (j == bi);
        const int ntile = nc * 4;
        float mx0 = -1e30f, mx1 = -1e30f;
        for (int t = 0; t < ntile; ++t) {
            if (diag) {
                int col = kb + 64 * (t >> 2) + nh * 32 + 8 * (t & 3) + 2 * tig;
                if (col > qi0) s[t][0] = -1e30f;
                if (col + 1 > qi0) s[t][1] = -1e30f;
                if (col > qi1) s[t][2] = -1e30f;
                if (col + 1 > qi1) s[t][3] = -1e30f;
            }
            mx0 = fmaxf(mx0, fmaxf(s[t][0], s[t][1]));
            mx1 = fmaxf(mx1, fmaxf(s[t][2], s[t][3]));
        }
        mx0 = fmaxf(mx0, __shfl_xor_sync(0xffffffffu, mx0, 1));
        mx0 = fmaxf(mx0, __shfl_xor_sync(0xffffffffu, mx0, 2));
        mx1 = fmaxf(mx1, __shfl_xor_sync(0xffffffffu, mx1, 1));
        mx1 = fmaxf(mx1, __shfl_xor_sync(0xffffffffu, mx1, 2));
        float l0 = 0.f, l1 = 0.f;
        for (int t = 0; t < ntile; ++t) {
            float p0 = (s[t][0] <= -1e29f) ? 0.f : __expf(SCALE * (s[t][0] - mx0));
            float p1 = (s[t][1] <= -1e29f) ? 0.f : __expf(SCALE * (s[t][1] - mx0));
            float p2 = (s[t][2] <= -1e29f) ? 0.f : __expf(SCALE * (s[t][2] - mx1));
            float p3 = (s[t][3] <= -1e29f) ? 0.f : __expf(SCALE * (s[t][3] - mx1));
            s[t][0] = p0; s[t][1] = p1; s[t][2] = p2; s[t][3] = p3;
            l0 += p0 + p1;
            l1 += p2 + p3;
        }
        l0 += __shfl_xor_sync(0xffffffffu, l0, 1);
        l0 += __shfl_xor_sync(0xffffffffu, l0, 2);
        l1 += __shfl_xor_sync(0xffffffffu, l1, 1);
        l1 += __shfl_xor_sync(0xffffffffu, l1, 2);
        if (tig == 0) {
            sma[ARED + row0 * 2 + nh] = mx0;
            sma[ARED + 128 + row0 * 2 + nh] = l0;
            sma[ARED + (row0 + 8) * 2 + nh] = mx1;
            sma[ARED + 128 + (row0 + 8) * 2 + nh] = l1;
        }
        __syncthreads();
        {
            float mo0 = sma[ARED + row0 * 2 + (nh ^ 1)];
            float lo0 = sma[ARED + 128 + row0 * 2 + (nh ^ 1)];
            float mo1 = sma[ARED + (row0 + 8) * 2 + (nh ^ 1)];
            float lo1 = sma[ARED + 128 + (row0 + 8) * 2 + (nh ^ 1)];
            float M0 = fmaxf(mx0, mo0), M1 = fmaxf(mx1, mo1);
            float cc0 = __expf(SCALE * (mx0 - M0)), co0 = __expf(SCALE * (mo0 - M0));
            float cc1 = __expf(SCALE * (mx1 - M1)), co1 = __expf(SCALE * (mo1 - M1));
            float f0 = cc0 / (l0 * cc0 + lo0 * co0 + 1e-30f);
            float f1 = cc1 / (l1 * cc1 + lo1 * co1 + 1e-30f);
            for (int t = 0; t < ntile; ++t) {
                int col = 64 * (t >> 2) + nh * 32 + 8 * (t & 3) + 2 * tig;
                uint32_t a0 = sb + (AP + ms * 4288 + g * 268 + col) * 4;
                asm volatile("st.shared.v2.b32 [%0], {%1,%2};"
                             :: "r"(a0), "r"(f2tf32(s[t][0] * f0)),
                                "r"(f2tf32(s[t][1] * f0)) : "memory");
                asm volatile("st.shared.v2.b32 [%0], {%1,%2};"
                             :: "r"(a0 + 8 * 268 * 4), "r"(f2tf32(s[t][2] * f1)),
                                "r"(f2tf32(s[t][3] * f1)) : "memory");
            }
        }
        __syncthreads();

        // ---- PV chunks ----
        for (int c = 0; c < nc; ++c) {
            cpa_wait0();
            __syncthreads();
            const uint32_t nb = sb + (cur ? AB0 : AB1) * 4;
            if (c + 1 < nc) {
                const int ka = kb + (c + 1) * 64;
#pragma unroll
                for (int i = 0; i < 8; ++i)
                    cpa16(nb + v_do[i], Vtb + (size_t)v_r[i] * Sc + ka + v_c[i]);
            } else if (j < bi) {
                const int ka = (j + 1) * BSZ;
#pragma unroll
                for (int i = 0; i < 8; ++i)
                    cpa16(nb + k_do[i], Kb + (size_t)(ka + k_r[i]) * Hc + k_c[i]);
            }
            cpa_commit();

            const uint32_t bufb = sb + (cur ? AB1 : AB0) * 4;
#pragma unroll
            for (int ks = 0; ks < 8; ++ks) {
                uint32_t af[4];
                ldsm_x4(af, aP + (c * 64 + ks * 8) * 4);
#pragma unroll
                for (int p = 0; p < 4; ++p) {
                    uint32_t bf[4];
                    ldsm_x4(bf, bufb + bVo[p] + ks * 32);
                    mma_tf32(o[2 * p], af, bf[0], bf[1]);
                    mma_tf32(o[2 * p + 1], af, bf[2], bf[3]);
                }
            }
            cur ^= 1;
        }
    }

    // epilogue: tf32-rounded output (feeds raw-bit Wo GEMM)
    const float invn = 1.f / ((float)(bi + 1) + 1e-6f);
#pragma unroll
    for (int u = 0; u < 8; ++u) {
        int d = nh * 64 + 16 * (u >> 1) + 8 * (u & 1) + 2 * tig;
        *(float2*)(O + base + (size_t)qi0 * Hc + d) =
            make_float2(rnd_tf32(o[u][0] * invn), rnd_tf32(o[u][1] * invn));
        *(float2*)(O + base + (size_t)qi1 * Hc + d) =
            make_float2(rnd_tf32(o[u][2] * invn), rnd_tf32(o[u][3] * invn));
    }
}

// ---------------------------------------------------------------------------
extern "C" void kernel_launch(void* const* d_in, const int* in_sizes, int n_in,
                              void* d_out, int out_size) {
    const float* hs = (const float*)d_in[0];
    const float* Wq = (const float*)d_in[1];
    const float* Wk = (const float*)d_in[2];
    const float* Wv = (const float*)d_in[3];
    const float* Wo = (const float*)d_in[4];
    float* out = (float*)d_out;

    float *qp, *kp, *vtp, *aop, *hsr, *wr;
    cudaGetSymbolAddress((void**)&qp, g_q);
    cudaGetSymbolAddress((void**)&kp, g_k);
    cudaGetSymbolAddress((void**)&vtp, g_vt);
    cudaGetSymbolAddress((void**)&aop, g_ao);
    cudaGetSymbolAddress((void**)&hsr, g_hsr);
    cudaGetSymbolAddress((void**)&wr, g_wr);
    float* wqr = wr;
    float* wkr = wr + (size_t)Hc * Hc;
    float* wvr = wr + 2 * (size_t)Hc * Hc;
    float* wor = wr + 3 * (size_t)Hc * Hc;

    static int smem_set = 0;
    if (!smem_set) {
        cudaFuncSetAttribute(gemm_mma, cudaFuncAttributeMaxDynamicSharedMemorySize,
                             GEMM_SMEM);
        cudaFuncSetAttribute(attn_mma, cudaFuncAttributeMaxDynamicSharedMemorySize,
                             ATTN_SMEM);
        smem_set = 1;
    }

    const int nHS4 = Bc * Sc * Hc / 4;
    const int nW4 = Hc * Hc / 4;
    round_k<<<nHS4 / 256, 256>>>(hs, hsr, nHS4);
    round_k<<<nW4 / 256, 256>>>(Wq, wqr, nW4);
    round_k<<<nW4 / 256, 256>>>(Wk, wkr, nW4);
    round_k<<<nW4 / 256, 256>>>(Wv, wvr, nW4);
    round_k<<<nW4 / 256, 256>>>(Wo, wor, nW4);

    dim3 gg(Hc / 128, Mc / 128);  // (16, 32)
    gemm_mma<<<gg, 256, GEMM_SMEM>>>(hsr, wqr, qp, Hc, Hc, 1);
    gemm_mma<<<gg, 256, GEMM_SMEM>>>(hsr, wkr, kp, Hc, Hc, 1);
    gemm_mma<<<gg, 256, GEMM_SMEM>>>(hsr, wvr, vtp, Hc, Hc, 2);

    dim3 ga(32, NHc, Bc);  // (32, 16, 2)
    attn_mma<<<ga, 256, ATTN_SMEM>>>(qp, kp, vtp, aop);

    gemm_mma<<<gg, 256, GEMM_SMEM>>>(aop, wor, out, Hc, Hc, 0);
}

// round 9
// speedup vs baseline: 3.8903x; 1.0880x over previous
#include <cuda_runtime.h>
#include <cstdint>
#include <math.h>

// Problem constants
static constexpr int Bc = 2, Sc = 2048, Hc = 2048, NHc = 16, HDc = 128, BSZ = 256;
static constexpr int Mc = Bc * Sc;  // 4096
static constexpr float SCALE = 0.08838834764831845f;  // 1/sqrt(128)

// Scratch (device globals — no allocation allowed)
__device__ float g_q[Bc * Sc * Hc];
__device__ float g_k[Bc * Sc * Hc];
__device__ float g_vt[Bc * Sc * Hc];      // V transposed: [b, h, d, s]
__device__ float g_ao[Bc * Sc * Hc];
__device__ float g_hsr[Bc * Sc * Hc];     // tf32-rounded hidden_states
__device__ float g_wr[4][Hc * Hc];        // tf32-rounded Wq,Wk,Wv,Wo (contiguous)

// ---------------------------------------------------------------------------
// helpers
// ---------------------------------------------------------------------------
__device__ __forceinline__ uint32_t smem_u32(const void* p) {
    uint32_t a;
    asm("{ .reg .u64 t; cvta.to.shared.u64 t, %1; cvt.u32.u64 %0, t; }"
        : "=r"(a) : "l"(p));
    return a;
}
__device__ __forceinline__ uint32_t f2tf32(float x) {
    uint32_t r;
    asm("cvt.rna.tf32.f32 %0, %1;" : "=r"(r) : "f"(x));
    return r;
}
__device__ __forceinline__ float rnd_tf32(float x) {
    return __uint_as_float(f2tf32(x));
}
__device__ __forceinline__ void ldsm_x4(uint32_t* r, uint32_t addr) {
    asm volatile("ldmatrix.sync.aligned.m8n8.x4.shared.b16 {%0,%1,%2,%3}, [%4];"
                 : "=r"(r[0]), "=r"(r[1]), "=r"(r[2]), "=r"(r[3]) : "r"(addr));
}
__device__ __forceinline__ void mma_tf32(float* d, const uint32_t* a,
                                         uint32_t b0, uint32_t b1) {
    asm volatile(
        "mma.sync.aligned.m16n8k8.row.col.f32.tf32.tf32.f32 "
        "{%0,%1,%2,%3}, {%4,%5,%6,%7}, {%8,%9}, {%0,%1,%2,%3};"
        : "+f"(d[0]), "+f"(d[1]), "+f"(d[2]), "+f"(d[3])
        : "r"(a[0]), "r"(a[1]), "r"(a[2]), "r"(a[3]), "r"(b0), "r"(b1));
}
__device__ __forceinline__ void cpa16(uint32_t dst, const void* src) {
    asm volatile("cp.async.cg.shared.global [%0], [%1], 16;"
                 :: "r"(dst), "l"(src) : "memory");
}
__device__ __forceinline__ void cpa_commit() {
    asm volatile("cp.async.commit_group;" ::: "memory");
}
__device__ __forceinline__ void cpa_wait1() {
    asm volatile("cp.async.wait_group 1;" ::: "memory");
}
__device__ __forceinline__ void cpa_wait0() {
    asm volatile("cp.async.wait_group 0;" ::: "memory");
}

// ---------------------------------------------------------------------------
// tf32 pre-rounding, all 5 tensors in one launch.
// layout (float4 units): [0,2M) hs -> hsr; [2M,6M) weights -> g_wr contiguous.
// ---------------------------------------------------------------------------
__global__ __launch_bounds__(256) void round_all(const float* __restrict__ hs,
                                                 const float* __restrict__ Wq,
                                                 const float* __restrict__ Wk,
                                                 const float* __restrict__ Wv,
                                                 const float* __restrict__ Wo,
                                                 float* __restrict__ hsr,
                                                 float* __restrict__ wr) {
    const int nHS4 = Bc * Sc * Hc / 4;   // 2M
    const int nW4 = Hc * Hc / 4;         // 1M
    int i = blockIdx.x * blockDim.x + threadIdx.x;
    const float4* src;
    float4* dst;
    int idx;
    if (i < nHS4) {
        src = (const float4*)hs; dst = (float4*)hsr; idx = i;
    } else {
        int j = i - nHS4;
        int w = j / nW4;
        idx = j - w * nW4;
        src = (const float4*)(w == 0 ? Wq : w == 1 ? Wk : w == 2 ? Wv : Wo);
        dst = (float4*)wr + (size_t)w * nW4;
    }
    float4 v = src[idx];
    float4 r;
    r.x = rnd_tf32(v.x); r.y = rnd_tf32(v.y);
    r.z = rnd_tf32(v.z); r.w = rnd_tf32(v.w);
    dst[idx] = r;
}

// ---------------------------------------------------------------------------
// Shared GEMM machinery (tf32 mma.sync, cp.async 3-stage)
// ---------------------------------------------------------------------------
static constexpr int RSF = 36;
static constexpr int ATILE = 128 * RSF * 4;        // 18432 bytes
static constexpr int STAGE = 2 * ATILE;            // 36864 bytes
static constexpr int GEMM_SMEM = 3 * STAGE;        // 110592 bytes

struct GemmCore {
    uint32_t sb;
    const float* gA[4];
    const float* gB[4];
    uint32_t so[4];
    uint32_t aFragOff, bFragOff;
    float acc[4][4][4];

    __device__ __forceinline__ void init(uint32_t sb_, const float* A, const float* W,
                                         int m0, int n0, int Kd, int tid) {
        sb = sb_;
        const int lane = tid & 31, wid = tid >> 5;
        const int wm = wid >> 2, wn = wid & 3;
#pragma unroll
        for (int i = 0; i < 4; ++i) {
            int id = tid + i * 256;
            int row = id >> 3, ch = id & 7;
            gA[i] = A + (size_t)(m0 + row) * Kd + ch * 4;
            gB[i] = W + (size_t)(n0 + row) * Kd + ch * 4;
            so[i] = row * (RSF * 4) + ch * 16;
        }
        const int arow = wm * 64 + (lane & 7) + ((lane >> 3) & 1) * 8;
        aFragOff = arow * (RSF * 4) + ((lane >> 4) & 1) * 16;
        const int brow = wn * 32 + (lane & 7) + ((lane >> 4) & 1) * 8;
        bFragOff = brow * (RSF * 4) + ((lane >> 3) & 1) * 16;
#pragma unroll
        for (int t = 0; t < 4; ++t)
#pragma unroll
            for (int u = 0; u < 4; ++u)
#pragma unroll
                for (int e = 0; e < 4; ++e) acc[t][u][e] = 0.f;
    }

    __device__ __forceinline__ void run(int NKB) {
#pragma unroll
        for (int s = 0; s < 2; ++s) {
            const uint32_t st = sb + s * STAGE;
#pragma unroll
            for (int i = 0; i < 4; ++i) {
                cpa16(st + so[i], gA[i] + s * 32);
                cpa16(st + ATILE + so[i], gB[i] + s * 32);
            }
            cpa_commit();
        }
        int stage = 0;
        for (int kb = 0; kb < NKB; ++kb) {
            cpa_wait1();
            __syncthreads();
            {
                int ns = stage + 2;
                if (ns >= 3) ns -= 3;
                if (kb + 2 < NKB) {
                    const uint32_t st = sb + ns * STAGE;
#pragma unroll
                    for (int i = 0; i < 4; ++i) {
                        cpa16(st + so[i], gA[i] + (kb + 2) * 32);
                        cpa16(st + ATILE + so[i], gB[i] + (kb + 2) * 32);
                    }
                }
                cpa_commit();
            }
            const uint32_t sA = sb + stage * STAGE;
            const uint32_t sB = sA + ATILE;
#pragma unroll
            for (int ks = 0; ks < 4; ++ks) {
                uint32_t af[4][4];
#pragma unroll
                for (int t = 0; t < 4; ++t)
                    ldsm_x4(af[t], sA + aFragOff + t * (16 * RSF * 4) + ks * 32);
                uint32_t bf[2][4];
#pragma unroll
                for (int p = 0; p < 2; ++p)
                    ldsm_x4(bf[p], sB + bFragOff + p * (16 * RSF * 4) + ks * 32);
#pragma unroll
                for (int t = 0; t < 4; ++t) {
                    mma_tf32(acc[t][0], af[t], bf[0][0], bf[0][1]);
                    mma_tf32(acc[t][1], af[t], bf[0][2], bf[0][3]);
                    mma_tf32(acc[t][2], af[t], bf[1][0], bf[1][1]);
                    mma_tf32(acc[t][3], af[t], bf[1][2], bf[1][3]);
                }
            }
            if (++stage == 3) stage = 0;
        }
    }
};

// Merged Q/K/V projection GEMM. grid (48, 32): bx>>4 selects matrix.
__global__ __launch_bounds__(256, 2) void gemm_qkv(const float* __restrict__ A,
                                                   const float* __restrict__ Wbase,
                                                   float* __restrict__ Qo,
                                                   float* __restrict__ Ko,
                                                   float* __restrict__ Vto) {
    extern __shared__ __align__(128) char smem[];
    const int tid = threadIdx.x;
    const int widx = blockIdx.x >> 4;            // 0=Q,1=K,2=V
    const int n0 = (blockIdx.x & 15) * 128;
    const int m0 = blockIdx.y * 128;
    const float* W = Wbase + (size_t)widx * Hc * Hc;

    GemmCore gc;
    gc.init(smem_u32(smem), A, W, m0, n0, Hc, tid);
    gc.run(Hc / 32);

    const int lane = tid & 31, wid = tid >> 5;
    const int wm = wid >> 2, wn = wid & 3;
    const int crow = lane >> 2, ccol = (lane & 3) * 2;
    if (widx == 2) {
        // V: write transposed per head [b,h,d,s], tf32-rounded
#pragma unroll
        for (int t = 0; t < 4; ++t) {
            int r0 = m0 + wm * 64 + t * 16 + crow;
#pragma unroll
            for (int u = 0; u < 4; ++u) {
                int c = n0 + wn * 32 + u * 8 + ccol;
#pragma unroll
                for (int e = 0; e < 4; ++e) {
                    int r = r0 + (e >> 1) * 8;
                    int cc = c + (e & 1);
                    int bq = r >> 11, s = r & 2047;
                    int hh = cc >> 7, d = cc & 127;
                    Vto[(((size_t)bq * NHc + hh) * HDc + d) * Sc + s] =
                        rnd_tf32(gc.acc[t][u][e]);
                }
            }
        }
    } else {
        float* C = (widx == 0) ? Qo : Ko;
#pragma unroll
        for (int t = 0; t < 4; ++t) {
            int r0 = m0 + wm * 64 + t * 16 + crow;
#pragma unroll
            for (int u = 0; u < 4; ++u) {
                int c = n0 + wn * 32 + u * 8 + ccol;
                *(float2*)(C + (size_t)r0 * Hc + c) =
                    make_float2(rnd_tf32(gc.acc[t][u][0]), rnd_tf32(gc.acc[t][u][1]));
                *(float2*)(C + (size_t)(r0 + 8) * Hc + c) =
                    make_float2(rnd_tf32(gc.acc[t][u][2]), rnd_tf32(gc.acc[t][u][3]));
            }
        }
    }
}

// Output projection GEMM (plain fp32 epilogue).
__global__ __launch_bounds__(256, 2) void gemm_wo(const float* __restrict__ A,
                                                  const float* __restrict__ W,
                                                  float* __restrict__ C) {
    extern __shared__ __align__(128) char smem[];
    const int tid = threadIdx.x;
    const int n0 = blockIdx.x * 128;
    const int m0 = blockIdx.y * 128;

    GemmCore gc;
    gc.init(smem_u32(smem), A, W, m0, n0, Hc, tid);
    gc.run(Hc / 32);

    const int lane = tid & 31, wid = tid >> 5;
    const int wm = wid >> 2, wn = wid & 3;
    const int crow = lane >> 2, ccol = (lane & 3) * 2;
#pragma unroll
    for (int t = 0; t < 4; ++t) {
        int r0 = m0 + wm * 64 + t * 16 + crow;
#pragma unroll
        for (int u = 0; u < 4; ++u) {
            int c = n0 + wn * 32 + u * 8 + ccol;
            *(float2*)(C + (size_t)r0 * Hc + c) =
                make_float2(gc.acc[t][u][0], gc.acc[t][u][1]);
            *(float2*)(C + (size_t)(r0 + 8) * Hc + c) =
                make_float2(gc.acc[t][u][2], gc.acc[t][u][3]);
        }
    }
}

// ---------------------------------------------------------------------------
// Tensor-core block-softmax attention, 2-CTA/SM edition.
// Single KV buffer + per-64-key-chunk P buffer -> 87 KB smem, regs capped 128.
// smem (floats): Q[64*132]=8448 | KV[8704] | Pc[64*68]=4352 | red[256]
// ---------------------------------------------------------------------------
static constexpr int AQ = 0;
static constexpr int AB = 8448;
static constexpr int APc = 17152;
static constexpr int ARED = 21504;
static constexpr int ATTN_SMEM = 21760 * 4;  // 87040 bytes

__global__ __launch_bounds__(256, 2) void attn_mma(const float* __restrict__ Q,
                                                   const float* __restrict__ K,
                                                   const float* __restrict__ Vt,
                                                   float* __restrict__ O) {
    extern __shared__ __align__(1024) float sma[];
    const uint32_t sb = smem_u32(sma);
    const int tid = threadIdx.x, lane = tid & 31, wid = tid >> 5;
    const int ms = wid >> 1, nh = wid & 1, g = lane >> 2, tig = lane & 3;
    const int qt = 31 - blockIdx.x;  // heavy tiles first
    const int h = blockIdx.y, b = blockIdx.z;
    const int q0 = qt * 64, bi = qt >> 2, sp = qt & 3;
    const size_t base = (size_t)b * Sc * Hc + (size_t)h * HDc;
    const float* Kb = K + base;
    const float* Qb = Q + base;
    const float* Vtb = Vt + ((size_t)(b * NHc + h) * HDc) * Sc;

    // load-slot geometry (computed, not stored in arrays)
    const int rowK = tid >> 5, colK = (tid & 31) * 4;          // K: 64r x 128d
    const int rowV = tid >> 4, colV = (tid & 15) * 4;          // V: 128d x 64k
    const uint32_t kDst = sb + (AB + rowK * 132 + colK) * 4;
    const uint32_t vDst = sb + (AB + rowV * 68 + colV) * 4;

    // prologue: Q tile + K block0 chunk0
#pragma unroll
    for (int i = 0; i < 8; ++i)
        cpa16(sb + (AQ + (rowK + 8 * i) * 132 + colK) * 4,
              Qb + (size_t)(q0 + rowK + 8 * i) * Hc + colK);
#pragma unroll
    for (int i = 0; i < 8; ++i)
        cpa16(kDst + i * (8 * 132 * 4), Kb + (size_t)(rowK + 8 * i) * Hc + colK);
    cpa_commit();

    // fragment bases
    const int frow = (lane & 7) + ((lane >> 3) & 1) * 8;
    const uint32_t aQ = sb + ((AQ + (ms * 16 + frow) * 132 + ((lane >> 4) & 1) * 4) * 4);
    const int browk = (lane & 7) + ((lane >> 4) & 1) * 8;
    const uint32_t bcolk = ((lane >> 3) & 1) * 4;
    const uint32_t bK0 = sb + AB * 4 + ((nh * 32 + browk) * 132 + bcolk) * 4;
    const uint32_t bK1 = bK0 + 16 * 132 * 4;
    const uint32_t aPc = sb + ((APc + (ms * 16 + frow) * 68 + ((lane >> 4) & 1) * 4) * 4);
    uint32_t bV[4];
#pragma unroll
    for (int p = 0; p < 4; ++p)
        bV[p] = sb + AB * 4 + ((nh * 64 + p * 16 + browk) * 68 + bcolk) * 4;

    float o[8][4];
#pragma unroll
    for (int u = 0; u < 8; ++u)
#pragma unroll
        for (int e = 0; e < 4; ++e) o[u][e] = 0.f;

    const int row0 = ms * 16 + g;
    const int qi0 = q0 + row0, qi1 = qi0 + 8;

    for (int j = 0; j <= bi; ++j) {
        const int nc = (j < bi) ? 4 : (sp + 1);
        const int kb = j * BSZ;
        float s[16][4];
#pragma unroll
        for (int t = 0; t < 16; ++t)
#pragma unroll
            for (int e = 0; e < 4; ++e) s[t][e] = 0.f;

        // ---- QK chunks (single buffer: load -> wait -> compute -> sync -> next load)
        for (int c = 0; c < nc; ++c) {
            cpa_wait0();
            __syncthreads();
#pragma unroll
            for (int ks = 0; ks < 16; ++ks) {
                uint32_t af[4];
                ldsm_x4(af, aQ + ks * 32);
                uint32_t bf[4];
                ldsm_x4(bf, bK0 + ks * 32);
                mma_tf32(s[c * 4 + 0], af, bf[0], bf[1]);
                mma_tf32(s[c * 4 + 1], af, bf[2], bf[3]);
                ldsm_x4(bf, bK1 + ks * 32);
                mma_tf32(s[c * 4 + 2], af, bf[0], bf[1]);
                mma_tf32(s[c * 4 + 3], af, bf[2], bf[3]);
            }
            __syncthreads();
            if (c + 1 < nc) {
                const int ka = kb + (c + 1) * 64;
#pragma unroll
                for (int i = 0; i < 8; ++i)
                    cpa16(kDst + i * (8 * 132 * 4),
                          Kb + (size_t)(ka + rowK + 8 * i) * Hc + colK);
            } else {
#pragma unroll
                for (int i = 0; i < 8; ++i)
                    cpa16(vDst + i * (16 * 68 * 4),
                          Vtb + (size_t)(rowV + 16 * i) * Sc + kb + colV);
            }
            cpa_commit();
        }

        // ---- per-block softmax ----
        const bool diag = (j == bi);
        const int ntile = nc * 4;
        float mx0 = -1e30f, mx1 = -1e30f;
        for (int t = 0; t < ntile; ++t) {
            if (diag) {
                int col = kb + 64 * (t >> 2) + nh * 32 + 8 * (t & 3) + 2 * tig;
                if (col > qi0) s[t][0] = -1e30f;
                if (col + 1 > qi0) s[t][1] = -1e30f;
                if (col > qi1) s[t][2] = -1e30f;
                if (col + 1 > qi1) s[t][3] = -1e30f;
            }
            mx0 = fmaxf(mx0, fmaxf(s[t][0], s[t][1]));
            mx1 = fmaxf(mx1, fmaxf(s[t][2], s[t][3]));
        }
        mx0 = fmaxf(mx0, __shfl_xor_sync(0xffffffffu, mx0, 1));
        mx0 = fmaxf(mx0, __shfl_xor_sync(0xffffffffu, mx0, 2));
        mx1 = fmaxf(mx1, __shfl_xor_sync(0xffffffffu, mx1, 1));
        mx1 = fmaxf(mx1, __shfl_xor_sync(0xffffffffu, mx1, 2));
        float l0 = 0.f, l1 = 0.f;
        for (int t = 0; t < ntile; ++t) {
            float p0 = (s[t][0] <= -1e29f) ? 0.f : __expf(SCALE * (s[t][0] - mx0));
            float p1 = (s[t][1] <= -1e29f) ? 0.f : __expf(SCALE * (s[t][1] - mx0));
            float p2 = (s[t][2] <= -1e29f) ? 0.f : __expf(SCALE * (s[t][2] - mx1));
            float p3 = (s[t][3] <= -1e29f) ? 0.f : __expf(SCALE * (s[t][3] - mx1));
            s[t][0] = p0; s[t][1] = p1; s[t][2] = p2; s[t][3] = p3;
            l0 += p0 + p1;
            l1 += p2 + p3;
        }
        l0 += __shfl_xor_sync(0xffffffffu, l0, 1);
        l0 += __shfl_xor_sync(0xffffffffu, l0, 2);
        l1 += __shfl_xor_sync(0xffffffffu, l1, 1);
        l1 += __shfl_xor_sync(0xffffffffu, l1, 2);
        if (tig == 0) {
            sma[ARED + row0 * 2 + nh] = mx0;
            sma[ARED + 128 + row0 * 2 + nh] = l0;
            sma[ARED + (row0 + 8) * 2 + nh] = mx1;
            sma[ARED + 128 + (row0 + 8) * 2 + nh] = l1;
        }
        __syncthreads();
        float f0, f1;
        {
            float mo0 = sma[ARED + row0 * 2 + (nh ^ 1)];
            float lo0 = sma[ARED + 128 + row0 * 2 + (nh ^ 1)];
            float mo1 = sma[ARED + (row0 + 8) * 2 + (nh ^ 1)];
            float lo1 = sma[ARED + 128 + (row0 + 8) * 2 + (nh ^ 1)];
            float M0 = fmaxf(mx0, mo0), M1 = fmaxf(mx1, mo1);
            float cc0 = __expf(SCALE * (mx0 - M0)), co0 = __expf(SCALE * (mo0 - M0));
            float cc1 = __expf(SCALE * (mx1 - M1)), co1 = __expf(SCALE * (mo1 - M1));
            f0 = cc0 / (l0 * cc0 + lo0 * co0 + 1e-30f);
            f1 = cc1 / (l1 * cc1 + lo1 * co1 + 1e-30f);
        }

        // ---- PV chunks (write P chunk, wait V chunk, mma) ----
        for (int c = 0; c < nc; ++c) {
            // write this chunk's P (buffer free: previous chunk's ldsm done)
#pragma unroll
            for (int tt = 0; tt < 4; ++tt) {
                int t = c * 4 + tt;
                int col = nh * 32 + 8 * tt + 2 * tig;
                uint32_t a0 = sb + (APc + (ms * 16 + g) * 68 + col) * 4;
                asm volatile("st.shared.v2.b32 [%0], {%1,%2};"
                             :: "r"(a0), "r"(f2tf32(s[t][0] * f0)),
                                "r"(f2tf32(s[t][1] * f0)) : "memory");
                asm volatile("st.shared.v2.b32 [%0], {%1,%2};"
                             :: "r"(a0 + 8 * 68 * 4), "r"(f2tf32(s[t][2] * f1)),
                                "r"(f2tf32(s[t][3] * f1)) : "memory");
            }
            cpa_wait0();
            __syncthreads();
#pragma unroll
            for (int ks = 0; ks < 8; ++ks) {
                uint32_t af[4];
                ldsm_x4(af, aPc + ks * 32);
#pragma unroll
                for (int p = 0; p < 4; ++p) {
                    uint32_t bf[4];
                    ldsm_x4(bf, bV[p] + ks * 32);
                    mma_tf32(o[2 * p], af, bf[0], bf[1]);
                    mma_tf32(o[2 * p + 1], af, bf[2], bf[3]);
                }
            }
            __syncthreads();
            if (c + 1 < nc) {
                const int ka = kb + (c + 1) * 64;
#pragma unroll
                for (int i = 0; i < 8; ++i)
                    cpa16(vDst + i * (16 * 68 * 4),
                          Vtb + (size_t)(rowV + 16 * i) * Sc + ka + colV);
            } else if (j < bi) {
                const int ka = (j + 1) * BSZ;
#pragma unroll
                for (int i = 0; i < 8; ++i)
                    cpa16(kDst + i * (8 * 132 * 4),
                          Kb + (size_t)(ka + rowK + 8 * i) * Hc + colK);
            }
            cpa_commit();
        }
    }

    // epilogue: tf32-rounded output (feeds raw-bit Wo GEMM)
    const float invn = 1.f / ((float)(bi + 1) + 1e-6f);
#pragma unroll
    for (int u = 0; u < 8; ++u) {
        int d = nh * 64 + 16 * (u >> 1) + 8 * (u & 1) + 2 * tig;
        *(float2*)(O + base + (size_t)qi0 * Hc + d) =
            make_float2(rnd_tf32(o[u][0] * invn), rnd_tf32(o[u][1] * invn));
        *(float2*)(O + base + (size_t)qi1 * Hc + d) =
            make_float2(rnd_tf32(o[u][2] * invn), rnd_tf32(o[u][3] * invn));
    }
}

// ---------------------------------------------------------------------------
extern "C" void kernel_launch(void* const* d_in, const int* in_sizes, int n_in,
                              void* d_out, int out_size) {
    const float* hs = (const float*)d_in[0];
    const float* Wq = (const float*)d_in[1];
    const float* Wk = (const float*)d_in[2];
    const float* Wv = (const float*)d_in[3];
    const float* Wo = (const float*)d_in[4];
    float* out = (float*)d_out;

    float *qp, *kp, *vtp, *aop, *hsr, *wr;
    cudaGetSymbolAddress((void**)&qp, g_q);
    cudaGetSymbolAddress((void**)&kp, g_k);
    cudaGetSymbolAddress((void**)&vtp, g_vt);
    cudaGetSymbolAddress((void**)&aop, g_ao);
    cudaGetSymbolAddress((void**)&hsr, g_hsr);
    cudaGetSymbolAddress((void**)&wr, g_wr);
    float* wor = wr + 3 * (size_t)Hc * Hc;

    static int smem_set = 0;
    if (!smem_set) {
        cudaFuncSetAttribute(gemm_qkv, cudaFuncAttributeMaxDynamicSharedMemorySize,
                             GEMM_SMEM);
        cudaFuncSetAttribute(gemm_wo, cudaFuncAttributeMaxDynamicSharedMemorySize,
                             GEMM_SMEM);
        cudaFuncSetAttribute(attn_mma, cudaFuncAttributeMaxDynamicSharedMemorySize,
                             ATTN_SMEM);
        smem_set = 1;
    }

    const int nTot4 = (Bc * Sc * Hc + 4 * Hc * Hc) / 4;  // 6M
    round_all<<<nTot4 / 256, 256>>>(hs, Wq, Wk, Wv, Wo, hsr, wr);

    dim3 gq(48, Mc / 128);  // QKV merged: 1536 CTAs
    gemm_qkv<<<gq, 256, GEMM_SMEM>>>(hsr, wr, qp, kp, vtp);

    dim3 ga(32, NHc, Bc);
    attn_mma<<<ga, 256, ATTN_SMEM>>>(qp, kp, vtp, aop);

    dim3 gw(Hc / 128, Mc / 128);
    gemm_wo<<<gw, 256, GEMM_SMEM>>>(aop, wor, out);
}

// round 10
// speedup vs baseline: 4.0593x; 1.0434x over previous
#include <cuda_runtime.h>
#include <cstdint>
#include <math.h>

// Problem constants
static constexpr int Bc = 2, Sc = 2048, Hc = 2048, NHc = 16, HDc = 128, BSZ = 256;
static constexpr int Mc = Bc * Sc;  // 4096
static constexpr float SCALE = 0.08838834764831845f;  // 1/sqrt(128)

// Scratch (device globals — no allocation allowed)
__device__ float g_q[Bc * Sc * Hc];
__device__ float g_k[Bc * Sc * Hc];
__device__ float g_vt[Bc * Sc * Hc];      // V transposed: [b, h, d, s]
__device__ float g_ao[Bc * Sc * Hc];
__device__ float g_hsr[Bc * Sc * Hc];     // tf32-rounded hidden_states
__device__ float g_wr[4][Hc * Hc];        // tf32-rounded Wq,Wk,Wv,Wo (contiguous)

// ---------------------------------------------------------------------------
// helpers
// ---------------------------------------------------------------------------
__device__ __forceinline__ uint32_t smem_u32(const void* p) {
    uint32_t a;
    asm("{ .reg .u64 t; cvta.to.shared.u64 t, %1; cvt.u32.u64 %0, t; }"
        : "=r"(a) : "l"(p));
    return a;
}
__device__ __forceinline__ uint32_t f2tf32(float x) {
    uint32_t r;
    asm("cvt.rna.tf32.f32 %0, %1;" : "=r"(r) : "f"(x));
    return r;
}
__device__ __forceinline__ float rnd_tf32(float x) {
    return __uint_as_float(f2tf32(x));
}
__device__ __forceinline__ void ldsm_x4(uint32_t* r, uint32_t addr) {
    asm volatile("ldmatrix.sync.aligned.m8n8.x4.shared.b16 {%0,%1,%2,%3}, [%4];"
                 : "=r"(r[0]), "=r"(r[1]), "=r"(r[2]), "=r"(r[3]) : "r"(addr));
}
__device__ __forceinline__ void mma_tf32(float* d, const uint32_t* a,
                                         uint32_t b0, uint32_t b1) {
    asm volatile(
        "mma.sync.aligned.m16n8k8.row.col.f32.tf32.tf32.f32 "
        "{%0,%1,%2,%3}, {%4,%5,%6,%7}, {%8,%9}, {%0,%1,%2,%3};"
        : "+f"(d[0]), "+f"(d[1]), "+f"(d[2]), "+f"(d[3])
        : "r"(a[0]), "r"(a[1]), "r"(a[2]), "r"(a[3]), "r"(b0), "r"(b1));
}
__device__ __forceinline__ void cpa16(uint32_t dst, const void* src) {
    asm volatile("cp.async.cg.shared.global [%0], [%1], 16;"
                 :: "r"(dst), "l"(src) : "memory");
}
__device__ __forceinline__ void cpa_commit() {
    asm volatile("cp.async.commit_group;" ::: "memory");
}
__device__ __forceinline__ void cpa_wait1() {
    asm volatile("cp.async.wait_group 1;" ::: "memory");
}
__device__ __forceinline__ void cpa_wait0() {
    asm volatile("cp.async.wait_group 0;" ::: "memory");
}

// ---------------------------------------------------------------------------
// tf32 pre-rounding, all 5 tensors in one launch.
// ---------------------------------------------------------------------------
__global__ __launch_bounds__(256) void round_all(const float* __restrict__ hs,
                                                 const float* __restrict__ Wq,
                                                 const float* __restrict__ Wk,
                                                 const float* __restrict__ Wv,
                                                 const float* __restrict__ Wo,
                                                 float* __restrict__ hsr,
                                                 float* __restrict__ wr) {
    const int nHS4 = Bc * Sc * Hc / 4;   // 2M
    const int nW4 = Hc * Hc / 4;         // 1M
    int i = blockIdx.x * blockDim.x + threadIdx.x;
    const float4* src;
    float4* dst;
    int idx;
    if (i < nHS4) {
        src = (const float4*)hs; dst = (float4*)hsr; idx = i;
    } else {
        int j = i - nHS4;
        int w = j / nW4;
        idx = j - w * nW4;
        src = (const float4*)(w == 0 ? Wq : w == 1 ? Wk : w == 2 ? Wv : Wo);
        dst = (float4*)wr + (size_t)w * nW4;
    }
    float4 v = src[idx];
    float4 r;
    r.x = rnd_tf32(v.x); r.y = rnd_tf32(v.y);
    r.z = rnd_tf32(v.z); r.w = rnd_tf32(v.w);
    dst[idx] = r;
}

// ---------------------------------------------------------------------------
// Shared GEMM machinery (tf32 mma.sync, cp.async 3-stage). K baked to 2048:
// all slot strides are compile-time immediates -> minimal register footprint.
// ---------------------------------------------------------------------------
static constexpr int RSF = 36;
static constexpr int ATILE = 128 * RSF * 4;        // 18432 bytes
static constexpr int STAGE = 2 * ATILE;            // 36864 bytes
static constexpr int GEMM_SMEM = 3 * STAGE;        // 110592 bytes
static constexpr int KD = 2048;
static constexpr int NKBg = KD / 32;               // 64

struct GemmCore {
    uint32_t sb;
    const float* gA0;
    const float* gB0;
    uint32_t so0;
    uint32_t aFragOff, bFragOff;
    float acc[4][4][4];

    __device__ __forceinline__ void init(uint32_t sb_, const float* A, const float* W,
                                         int m0, int n0, int tid) {
        sb = sb_;
        const int lane = tid & 31, wid = tid >> 5;
        const int wm = wid >> 2, wn = wid & 3;
        const int row = tid >> 3, ch = tid & 7;
        gA0 = A + (size_t)(m0 + row) * KD + ch * 4;
        gB0 = W + (size_t)(n0 + row) * KD + ch * 4;
        so0 = row * (RSF * 4) + ch * 16;
        const int arow = wm * 64 + (lane & 7) + ((lane >> 3) & 1) * 8;
        aFragOff = arow * (RSF * 4) + ((lane >> 4) & 1) * 16;
        const int brow = wn * 32 + (lane & 7) + ((lane >> 4) & 1) * 8;
        bFragOff = brow * (RSF * 4) + ((lane >> 3) & 1) * 16;
#pragma unroll
        for (int t = 0; t < 4; ++t)
#pragma unroll
            for (int u = 0; u < 4; ++u)
#pragma unroll
                for (int e = 0; e < 4; ++e) acc[t][u][e] = 0.f;
    }

    __device__ __forceinline__ void ld_stage(uint32_t st, int kb) {
#pragma unroll
        for (int i = 0; i < 4; ++i) {
            cpa16(st + so0 + i * (32 * RSF * 4), gA0 + kb * 32 + i * (32 * KD));
            cpa16(st + ATILE + so0 + i * (32 * RSF * 4), gB0 + kb * 32 + i * (32 * KD));
        }
        cpa_commit();
    }

    __device__ __forceinline__ void run() {
        ld_stage(sb, 0);
        ld_stage(sb + STAGE, 1);
        int stage = 0;
        for (int kb = 0; kb < NKBg; ++kb) {
            cpa_wait1();
            __syncthreads();
            {
                int ns = stage + 2;
                if (ns >= 3) ns -= 3;
                if (kb + 2 < NKBg) {
                    ld_stage(sb + ns * STAGE, kb + 2);
                } else {
                    cpa_commit();
                }
            }
            const uint32_t sA = sb + stage * STAGE;
            const uint32_t sB = sA + ATILE;
#pragma unroll
            for (int ks = 0; ks < 4; ++ks) {
                uint32_t af[4][4];
#pragma unroll
                for (int t = 0; t < 4; ++t)
                    ldsm_x4(af[t], sA + aFragOff + t * (16 * RSF * 4) + ks * 32);
                uint32_t bf[2][4];
#pragma unroll
                for (int p = 0; p < 2; ++p)
                    ldsm_x4(bf[p], sB + bFragOff + p * (16 * RSF * 4) + ks * 32);
#pragma unroll
                for (int t = 0; t < 4; ++t) {
                    mma_tf32(acc[t][0], af[t], bf[0][0], bf[0][1]);
                    mma_tf32(acc[t][1], af[t], bf[0][2], bf[0][3]);
                    mma_tf32(acc[t][2], af[t], bf[1][0], bf[1][1]);
                    mma_tf32(acc[t][3], af[t], bf[1][2], bf[1][3]);
                }
            }
            if (++stage == 3) stage = 0;
        }
    }
};

// Merged Q/K/V projection GEMM, half of heads per launch.
// grid (24, 32): bx>>3 = widx (0=Q,1=K,2=V), (bx&7)+ntOff = n-tile = head.
__global__ __launch_bounds__(256, 2) void gemm_qkv(const float* __restrict__ A,
                                                   const float* __restrict__ Wbase,
                                                   float* __restrict__ Qo,
                                                   float* __restrict__ Ko,
                                                   float* __restrict__ Vto,
                                                   int ntOff) {
    extern __shared__ __align__(128) char smem[];
    const int tid = threadIdx.x;
    const int widx = blockIdx.x >> 3;
    const int n0 = ((blockIdx.x & 7) + ntOff) * 128;
    const int m0 = blockIdx.y * 128;
    const float* W = Wbase + (size_t)widx * Hc * Hc;

    GemmCore gc;
    gc.init(smem_u32(smem), A, W, m0, n0, tid);
    gc.run();

    const int lane = tid & 31, wid = tid >> 5;
    const int wm = wid >> 2, wn = wid & 3;
    const int crow = lane >> 2, ccol = (lane & 3) * 2;
    if (widx == 2) {
        // V: write transposed per head [b,h,d,s], tf32-rounded
#pragma unroll
        for (int t = 0; t < 4; ++t) {
            int r0 = m0 + wm * 64 + t * 16 + crow;
#pragma unroll
            for (int u = 0; u < 4; ++u) {
                int c = n0 + wn * 32 + u * 8 + ccol;
#pragma unroll
                for (int e = 0; e < 4; ++e) {
                    int r = r0 + (e >> 1) * 8;
                    int cc = c + (e & 1);
                    int bq = r >> 11, s = r & 2047;
                    int hh = cc >> 7, d = cc & 127;
                    Vto[(((size_t)bq * NHc + hh) * HDc + d) * Sc + s] =
                        rnd_tf32(gc.acc[t][u][e]);
                }
            }
        }
    } else {
        float* C = (widx == 0) ? Qo : Ko;
#pragma unroll
        for (int t = 0; t < 4; ++t) {
            int r0 = m0 + wm * 64 + t * 16 + crow;
#pragma unroll
            for (int u = 0; u < 4; ++u) {
                int c = n0 + wn * 32 + u * 8 + ccol;
                *(float2*)(C + (size_t)r0 * Hc + c) =
                    make_float2(rnd_tf32(gc.acc[t][u][0]), rnd_tf32(gc.acc[t][u][1]));
                *(float2*)(C + (size_t)(r0 + 8) * Hc + c) =
                    make_float2(rnd_tf32(gc.acc[t][u][2]), rnd_tf32(gc.acc[t][u][3]));
            }
        }
    }
}

// Output projection GEMM (plain fp32 epilogue).
__global__ __launch_bounds__(256, 2) void gemm_wo(const float* __restrict__ A,
                                                  const float* __restrict__ W,
                                                  float* __restrict__ C) {
    extern __shared__ __align__(128) char smem[];
    const int tid = threadIdx.x;
    const int n0 = blockIdx.x * 128;
    const int m0 = blockIdx.y * 128;

    GemmCore gc;
    gc.init(smem_u32(smem), A, W, m0, n0, tid);
    gc.run();

    const int lane = tid & 31, wid = tid >> 5;
    const int wm = wid >> 2, wn = wid & 3;
    const int crow = lane >> 2, ccol = (lane & 3) * 2;
#pragma unroll
    for (int t = 0; t < 4; ++t) {
        int r0 = m0 + wm * 64 + t * 16 + crow;
#pragma unroll
        for (int u = 0; u < 4; ++u) {
            int c = n0 + wn * 32 + u * 8 + ccol;
            *(float2*)(C + (size_t)r0 * Hc + c) =
                make_float2(gc.acc[t][u][0], gc.acc[t][u][1]);
            *(float2*)(C + (size_t)(r0 + 8) * Hc + c) =
                make_float2(gc.acc[t][u][2], gc.acc[t][u][3]);
        }
    }
}

// ---------------------------------------------------------------------------
// Tensor-core block-softmax attention, 2-CTA/SM, head-half per launch.
// smem (floats): Q[64*132]=8448 | KV[8704] | Pc[64*68]=4352 | red[256]
// ---------------------------------------------------------------------------
static constexpr int AQ = 0;
static constexpr int AB = 8448;
static constexpr int APc = 17152;
static constexpr int ARED = 21504;
static constexpr int ATTN_SMEM = 21760 * 4;  // 87040 bytes

__global__ __launch_bounds__(256, 2) void attn_mma(const float* __restrict__ Q,
                                                   const float* __restrict__ K,
                                                   const float* __restrict__ Vt,
                                                   float* __restrict__ O,
                                                   int hOff) {
    extern __shared__ __align__(1024) float sma[];
    const uint32_t sb = smem_u32(sma);
    const int tid = threadIdx.x, lane = tid & 31, wid = tid >> 5;
    const int ms = wid >> 1, nh = wid & 1, g = lane >> 2, tig = lane & 3;
    const int qt = 31 - blockIdx.x;  // heavy tiles first
    const int h = blockIdx.y + hOff, b = blockIdx.z;
    const int q0 = qt * 64, bi = qt >> 2, sp = qt & 3;
    const size_t base = (size_t)b * Sc * Hc + (size_t)h * HDc;
    const float* Kb = K + base;
    const float* Qb = Q + base;
    const float* Vtb = Vt + ((size_t)(b * NHc + h) * HDc) * Sc;

    const int rowK = tid >> 5, colK = (tid & 31) * 4;          // K: 64r x 128d
    const int rowV = tid >> 4, colV = (tid & 15) * 4;          // V: 128d x 64k
    const uint32_t kDst = sb + (AB + rowK * 132 + colK) * 4;
    const uint32_t vDst = sb + (AB + rowV * 68 + colV) * 4;

    // prologue: Q tile + K block0 chunk0
#pragma unroll
    for (int i = 0; i < 8; ++i)
        cpa16(sb + (AQ + (rowK + 8 * i) * 132 + colK) * 4,
              Qb + (size_t)(q0 + rowK + 8 * i) * Hc + colK);
#pragma unroll
    for (int i = 0; i < 8; ++i)
        cpa16(kDst + i * (8 * 132 * 4), Kb + (size_t)(rowK + 8 * i) * Hc + colK);
    cpa_commit();

    const int frow = (lane & 7) + ((lane >> 3) & 1) * 8;
    const uint32_t aQ = sb + ((AQ + (ms * 16 + frow) * 132 + ((lane >> 4) & 1) * 4) * 4);
    const int browk = (lane & 7) + ((lane >> 4) & 1) * 8;
    const uint32_t bcolk = ((lane >> 3) & 1) * 4;
    const uint32_t bK0 = sb + AB * 4 + ((nh * 32 + browk) * 132 + bcolk) * 4;
    const uint32_t bK1 = bK0 + 16 * 132 * 4;
    const uint32_t aPc = sb + ((APc + (ms * 16 + frow) * 68 + ((lane >> 4) & 1) * 4) * 4);
    uint32_t bV[4];
#pragma unroll
    for (int p = 0; p < 4; ++p)
        bV[p] = sb + AB * 4 + ((nh * 64 + p * 16 + browk) * 68 + bcolk) * 4;

    float o[8][4];
#pragma unroll
    for (int u = 0; u < 8; ++u)
#pragma unroll
        for (int e = 0; e < 4; ++e) o[u][e] = 0.f;

    const int row0 = ms * 16 + g;
    const int qi0 = q0 + row0, qi1 = qi0 + 8;

    for (int j = 0; j <= bi; ++j) {
        const int nc = (j < bi) ? 4 : (sp + 1);
        const int kb = j * BSZ;
        float s[16][4];
#pragma unroll
        for (int t = 0; t < 16; ++t)
#pragma unroll
            for (int e = 0; e < 4; ++e) s[t][e] = 0.f;

        // ---- QK chunks ----
        for (int c = 0; c < nc; ++c) {
            cpa_wait0();
            __syncthreads();
#pragma unroll
            for (int ks = 0; ks < 16; ++ks) {
                uint32_t af[4];
                ldsm_x4(af, aQ + ks * 32);
                uint32_t bf[4];
                ldsm_x4(bf, bK0 + ks * 32);
                mma_tf32(s[c * 4 + 0], af, bf[0], bf[1]);
                mma_tf32(s[c * 4 + 1], af, bf[2], bf[3]);
                ldsm_x4(bf, bK1 + ks * 32);
                mma_tf32(s[c * 4 + 2], af, bf[0], bf[1]);
                mma_tf32(s[c * 4 + 3], af, bf[2], bf[3]);
            }
            __syncthreads();
            if (c + 1 < nc) {
                const int ka = kb + (c + 1) * 64;
#pragma unroll
                for (int i = 0; i < 8; ++i)
                    cpa16(kDst + i * (8 * 132 * 4),
                          Kb + (size_t)(ka + rowK + 8 * i) * Hc + colK);
            } else {
#pragma unroll
                for (int i = 0; i < 8; ++i)
                    cpa16(vDst + i * (16 * 68 * 4),
                          Vtb + (size_t)(rowV + 16 * i) * Sc + kb + colV);
            }
            cpa_commit();
        }

        // ---- per-block softmax ----
        const bool diag = (j == bi);
        const int ntile = nc * 4;
        float mx0 = -1e30f, mx1 = -1e30f;
        for (int t = 0; t < ntile; ++t) {
            if (diag) {
                int col = kb + 64 * (t >> 2) + nh * 32 + 8 * (t & 3) + 2 * tig;
                if (col > qi0) s[t][0] = -1e30f;
                if (col + 1 > qi0) s[t][1] = -1e30f;
                if (col > qi1) s[t][2] = -1e30f;
                if (col + 1 > qi1) s[t][3] = -1e30f;
            }
            mx0 = fmaxf(mx0, fmaxf(s[t][0], s[t][1]));
            mx1 = fmaxf(mx1, fmaxf(s[t][2], s[t][3]));
        }
        mx0 = fmaxf(mx0, __shfl_xor_sync(0xffffffffu, mx0, 1));
        mx0 = fmaxf(mx0, __shfl_xor_sync(0xffffffffu, mx0, 2));
        mx1 = fmaxf(mx1, __shfl_xor_sync(0xffffffffu, mx1, 1));
        mx1 = fmaxf(mx1, __shfl_xor_sync(0xffffffffu, mx1, 2));
        float l0 = 0.f, l1 = 0.f;
        for (int t = 0; t < ntile; ++t) {
            float p0 = (s[t][0] <= -1e29f) ? 0.f : __expf(SCALE * (s[t][0] - mx0));
            float p1 = (s[t][1] <= -1e29f) ? 0.f : __expf(SCALE * (s[t][1] - mx0));
            float p2 = (s[t][2] <= -1e29f) ? 0.f : __expf(SCALE * (s[t][2] - mx1));
            float p3 = (s[t][3] <= -1e29f) ? 0.f : __expf(SCALE * (s[t][3] - mx1));
            s[t][0] = p0; s[t][1] = p1; s[t][2] = p2; s[t][3] = p3;
            l0 += p0 + p1;
            l1 += p2 + p3;
        }
        l0 += __shfl_xor_sync(0xffffffffu, l0, 1);
        l0 += __shfl_xor_sync(0xffffffffu, l0, 2);
        l1 += __shfl_xor_sync(0xffffffffu, l1, 1);
        l1 += __shfl_xor_sync(0xffffffffu, l1, 2);
        if (tig == 0) {
            sma[ARED + row0 * 2 + nh] = mx0;
            sma[ARED + 128 + row0 * 2 + nh] = l0;
            sma[ARED + (row0 + 8) * 2 + nh] = mx1;
            sma[ARED + 128 + (row0 + 8) * 2 + nh] = l1;
        }
        __syncthreads();
        float f0, f1;
        {
            float mo0 = sma[ARED + row0 * 2 + (nh ^ 1)];
            float lo0 = sma[ARED + 128 + row0 * 2 + (nh ^ 1)];
            float mo1 = sma[ARED + (row0 + 8) * 2 + (nh ^ 1)];
            float lo1 = sma[ARED + 128 + (row0 + 8) * 2 + (nh ^ 1)];
            float M0 = fmaxf(mx0, mo0), M1 = fmaxf(mx1, mo1);
            float cc0 = __expf(SCALE * (mx0 - M0)), co0 = __expf(SCALE * (mo0 - M0));
            float cc1 = __expf(SCALE * (mx1 - M1)), co1 = __expf(SCALE * (mo1 - M1));
            f0 = cc0 / (l0 * cc0 + lo0 * co0 + 1e-30f);
            f1 = cc1 / (l1 * cc1 + lo1 * co1 + 1e-30f);
        }

        // ---- PV chunks ----
        for (int c = 0; c < nc; ++c) {
#pragma unroll
            for (int tt = 0; tt < 4; ++tt) {
                int t = c * 4 + tt;
                int col = nh * 32 + 8 * tt + 2 * tig;
                uint32_t a0 = sb + (APc + (ms * 16 + g) * 68 + col) * 4;
                asm volatile("st.shared.v2.b32 [%0], {%1,%2};"
                             :: "r"(a0), "r"(f2tf32(s[t][0] * f0)),
                                "r"(f2tf32(s[t][1] * f0)) : "memory");
                asm volatile("st.shared.v2.b32 [%0], {%1,%2};"
                             :: "r"(a0 + 8 * 68 * 4), "r"(f2tf32(s[t][2] * f1)),
                                "r"(f2tf32(s[t][3] * f1)) : "memory");
            }
            cpa_wait0();
            __syncthreads();
#pragma unroll
            for (int ks = 0; ks < 8; ++ks) {
                uint32_t af[4];
                ldsm_x4(af, aPc + ks * 32);
#pragma unroll
                for (int p = 0; p < 4; ++p) {
                    uint32_t bf[4];
                    ldsm_x4(bf, bV[p] + ks * 32);
                    mma_tf32(o[2 * p], af, bf[0], bf[1]);
                    mma_tf32(o[2 * p + 1], af, bf[2], bf[3]);
                }
            }
            __syncthreads();
            if (c + 1 < nc) {
                const int ka = kb + (c + 1) * 64;
#pragma unroll
                for (int i = 0; i < 8; ++i)
                    cpa16(vDst + i * (16 * 68 * 4),
                          Vtb + (size_t)(rowV + 16 * i) * Sc + ka + colV);
            } else if (j < bi) {
                const int ka = (j + 1) * BSZ;
#pragma unroll
                for (int i = 0; i < 8; ++i)
                    cpa16(kDst + i * (8 * 132 * 4),
                          Kb + (size_t)(ka + rowK + 8 * i) * Hc + colK);
            }
            cpa_commit();
        }
    }

    // epilogue: tf32-rounded output (feeds raw-bit Wo GEMM)
    const float invn = 1.f / ((float)(bi + 1) + 1e-6f);
#pragma unroll
    for (int u = 0; u < 8; ++u) {
        int d = nh * 64 + 16 * (u >> 1) + 8 * (u & 1) + 2 * tig;
        *(float2*)(O + base + (size_t)qi0 * Hc + d) =
            make_float2(rnd_tf32(o[u][0] * invn), rnd_tf32(o[u][1] * invn));
        *(float2*)(O + base + (size_t)qi1 * Hc + d) =
            make_float2(rnd_tf32(o[u][2] * invn), rnd_tf32(o[u][3] * invn));
    }
}

// ---------------------------------------------------------------------------
extern "C" void kernel_launch(void* const* d_in, const int* in_sizes, int n_in,
                              void* d_out, int out_size) {
    const float* hs = (const float*)d_in[0];
    const float* Wq = (const float*)d_in[1];
    const float* Wk = (const float*)d_in[2];
    const float* Wv = (const float*)d_in[3];
    const float* Wo = (const float*)d_in[4];
    float* out = (float*)d_out;

    float *qp, *kp, *vtp, *aop, *hsr, *wr;
    cudaGetSymbolAddress((void**)&qp, g_q);
    cudaGetSymbolAddress((void**)&kp, g_k);
    cudaGetSymbolAddress((void**)&vtp, g_vt);
    cudaGetSymbolAddress((void**)&aop, g_ao);
    cudaGetSymbolAddress((void**)&hsr, g_hsr);
    cudaGetSymbolAddress((void**)&wr, g_wr);
    float* wor = wr + 3 * (size_t)Hc * Hc;

    static int init_done = 0;
    static cudaStream_t s2;
    static cudaEvent_t evR, ev1;
    if (!init_done) {
        cudaFuncSetAttribute(gemm_qkv, cudaFuncAttributeMaxDynamicSharedMemorySize,
                             GEMM_SMEM);
        cudaFuncSetAttribute(gemm_wo, cudaFuncAttributeMaxDynamicSharedMemorySize,
                             GEMM_SMEM);
        cudaFuncSetAttribute(attn_mma, cudaFuncAttributeMaxDynamicSharedMemorySize,
                             ATTN_SMEM);
        cudaStreamCreateWithFlags(&s2, cudaStreamNonBlocking);
        cudaEventCreateWithFlags(&evR, cudaEventDisableTiming);
        cudaEventCreateWithFlags(&ev1, cudaEventDisableTiming);
        init_done = 1;
    }

    const int nTot4 = (Bc * Sc * Hc + 4 * Hc * Hc) / 4;  // 6M
    round_all<<<nTot4 / 256, 256>>>(hs, Wq, Wk, Wv, Wo, hsr, wr);
    cudaEventRecord(evR, 0);
    cudaStreamWaitEvent(s2, evR, 0);

    dim3 gqh(24, Mc / 128);  // half of QKV: 768 CTAs
    dim3 gah(32, NHc / 2, Bc);
    // half B on second stream (heads 8-15)
    gemm_qkv<<<gqh, 256, GEMM_SMEM, s2>>>(hsr, wr, qp, kp, vtp, 8);
    attn_mma<<<gah, 256, ATTN_SMEM, s2>>>(qp, kp, vtp, aop, 8);
    cudaEventRecord(ev1, s2);
    // half A on default stream (heads 0-7)
    gemm_qkv<<<gqh, 256, GEMM_SMEM>>>(hsr, wr, qp, kp, vtp, 0);
    attn_mma<<<gah, 256, ATTN_SMEM>>>(qp, kp, vtp, aop, 0);
    cudaStreamWaitEvent(0, ev1, 0);

    dim3 gw(Hc / 128, Mc / 128);
    gemm_wo<<<gw, 256, GEMM_SMEM>>>(aop, wor, out);
}